// round 1
// baseline (speedup 1.0000x reference)
#include <cuda_runtime.h>
#include <math.h>

#define BATCH 32
#define S 2048
#define EPSLN 1e-5f
#define L2E 1.4426950408889634f   // log2(e)

// ---------------- scratch (no allocations allowed) ----------------
__device__ float g_q[BATCH * S];
__device__ float g_k[BATCH * S];
__device__ float g_v[BATCH * S];
__device__ float g_num[BATCH * S];
__device__ float g_act[BATCH * S];
__device__ float g_fc[BATCH * S];
__device__ float g_Z[BATCH];

__device__ __forceinline__ float ex2f(float x) {
    float y;
    asm("ex2.approx.f32 %0, %1;" : "=f"(y) : "f"(x));
    return y;
}

// ---------------- kernel 0: zero the Z accumulators ----------------
__global__ void zero_kernel() {
    if (threadIdx.x < BATCH) g_Z[threadIdx.x] = 0.0f;
}

// ---------------- kernel 1: fused QKV GEMM (out = x @ W^T) ----------------
// grid (S/128, BATCH/8, 3), block 128. Each thread: 1 output column, 8 batch rows.
// x rows cached in shared (two 1024-wide K chunks, 32KB), W streamed as float4.
__global__ void qkv_kernel(const float* __restrict__ x,
                           const float* __restrict__ Wq,
                           const float* __restrict__ Wk,
                           const float* __restrict__ Wv) {
    __shared__ float sx[8][1024];
    const float* W = (blockIdx.z == 0) ? Wq : (blockIdx.z == 1 ? Wk : Wv);
    float* out = (blockIdx.z == 0) ? g_q : (blockIdx.z == 1 ? g_k : g_v);

    const int b0 = blockIdx.y * 8;
    const int c  = blockIdx.x * 128 + threadIdx.x;

    float acc[8] = {0.f, 0.f, 0.f, 0.f, 0.f, 0.f, 0.f, 0.f};

    for (int kk = 0; kk < 2; kk++) {
        __syncthreads();
        for (int idx = threadIdx.x; idx < 8 * 1024; idx += 128) {
            int bb = idx >> 10, k = idx & 1023;
            sx[bb][k] = x[(b0 + bb) * S + kk * 1024 + k];
        }
        __syncthreads();

        const float4* Wr = (const float4*)(W + (size_t)c * S + kk * 1024);
        #pragma unroll 4
        for (int k4 = 0; k4 < 256; k4++) {
            float4 w = Wr[k4];
            #pragma unroll
            for (int bb = 0; bb < 8; bb++) {
                float4 xv = *(const float4*)&sx[bb][k4 * 4];
                acc[bb] = fmaf(w.x, xv.x, acc[bb]);
                acc[bb] = fmaf(w.y, xv.y, acc[bb]);
                acc[bb] = fmaf(w.z, xv.z, acc[bb]);
                acc[bb] = fmaf(w.w, xv.w, acc[bb]);
            }
        }
    }
    #pragma unroll
    for (int bb = 0; bb < 8; bb++) out[(b0 + bb) * S + c] = acc[bb];
}

// ---------------- kernel 2: attention (global softmax over outer product) ----------------
// valued[b,i] * Z_b = sum_j exp(q_i*k_j - M) * v_j ;  Z_b = sum_ij exp(q_i*k_j - M)
// grid (BATCH, S/256), block 256, 1 row-index i per thread.
__global__ void attn_kernel() {
    __shared__ float sq[S], sk[S], sv[S];
    __shared__ float rqmn[8], rqmx[8], rkmn[8], rkmx[8], rsum[8];
    __shared__ float sMl2e;

    const int b = blockIdx.x;
    const float* qg = g_q + b * S;
    const float* kg = g_k + b * S;
    const float* vg = g_v + b * S;

    const int tid = threadIdx.x;
    const int lane = tid & 31, wid = tid >> 5;

    float qmn = 3.0e38f, qmx = -3.0e38f, kmn = 3.0e38f, kmx = -3.0e38f;
    for (int idx = tid; idx < S; idx += 256) {
        float qv = qg[idx], kv = kg[idx];
        sq[idx] = qv; sk[idx] = kv; sv[idx] = vg[idx];
        qmn = fminf(qmn, qv); qmx = fmaxf(qmx, qv);
        kmn = fminf(kmn, kv); kmx = fmaxf(kmx, kv);
    }
    #pragma unroll
    for (int off = 16; off > 0; off >>= 1) {
        qmn = fminf(qmn, __shfl_xor_sync(0xffffffffu, qmn, off));
        qmx = fmaxf(qmx, __shfl_xor_sync(0xffffffffu, qmx, off));
        kmn = fminf(kmn, __shfl_xor_sync(0xffffffffu, kmn, off));
        kmx = fmaxf(kmx, __shfl_xor_sync(0xffffffffu, kmx, off));
    }
    if (lane == 0) { rqmn[wid] = qmn; rqmx[wid] = qmx; rkmn[wid] = kmn; rkmx[wid] = kmx; }
    __syncthreads();
    if (tid == 0) {
        float a = rqmn[0], bq = rqmx[0], cK = rkmn[0], dK = rkmx[0];
        #pragma unroll
        for (int w = 1; w < 8; w++) {
            a = fminf(a, rqmn[w]); bq = fmaxf(bq, rqmx[w]);
            cK = fminf(cK, rkmn[w]); dK = fmaxf(dK, rkmx[w]);
        }
        // max over i,j of q_i*k_j is attained at a corner (bilinear in endpoints)
        float M = fmaxf(fmaxf(a * cK, a * dK), fmaxf(bq * cK, bq * dK));
        sMl2e = M * L2E;
    }
    __syncthreads();

    const float mM = sMl2e;
    const int i = blockIdx.y * 256 + tid;
    const float qi = sq[i] * L2E;

    float num = 0.f, rs = 0.f;
    #pragma unroll 4
    for (int j4 = 0; j4 < S / 4; j4++) {
        float4 k4 = *(const float4*)&sk[j4 * 4];
        float4 v4 = *(const float4*)&sv[j4 * 4];
        float e0 = ex2f(fmaf(qi, k4.x, -mM));
        float e1 = ex2f(fmaf(qi, k4.y, -mM));
        float e2 = ex2f(fmaf(qi, k4.z, -mM));
        float e3 = ex2f(fmaf(qi, k4.w, -mM));
        num = fmaf(e0, v4.x, num); rs += e0;
        num = fmaf(e1, v4.y, num); rs += e1;
        num = fmaf(e2, v4.z, num); rs += e2;
        num = fmaf(e3, v4.w, num); rs += e3;
    }
    g_num[b * S + i] = num;

    #pragma unroll
    for (int off = 16; off > 0; off >>= 1)
        rs += __shfl_xor_sync(0xffffffffu, rs, off);
    if (lane == 0) rsum[wid] = rs;
    __syncthreads();
    if (tid == 0) {
        float tot = rsum[0];
        #pragma unroll
        for (int w = 1; w < 8; w++) tot += rsum[w];
        atomicAdd(&g_Z[b], tot);
    }
}

// ---------------- kernel 3: divide by Z + OptimActivation ----------------
// grid 256, block 256
__global__ void act_kernel(const float* __restrict__ p2) {
    const int idx = blockIdx.x * 256 + threadIdx.x;
    const int b = idx >> 11;

    // softmax over 5 activation params (tiny, per-thread, L1-cached)
    float p[5];
    #pragma unroll
    for (int t = 0; t < 5; t++) p[t] = p2[t];
    float pm = p[0];
    #pragma unroll
    for (int t = 1; t < 5; t++) pm = fmaxf(pm, p[t]);
    float pe[5], psum = 0.f;
    #pragma unroll
    for (int t = 0; t < 5; t++) { pe[t] = ex2f((p[t] - pm) * L2E); psum += pe[t]; }
    const float inv = __fdividef(1.0f, psum);
    const float ps0 = pe[0] * inv, ps1 = pe[1] * inv, ps2 = pe[2] * inv;

    const float val = __fdividef(g_num[idx], g_Z[b]);
    const float sig = __fdividef(1.0f, 1.0f + ex2f(-val * L2E));
    g_act[idx] = sig * val * ps0 + __sinf(val) * ps1 + val * ps2;
}

// ---------------- kernel 4: fc2 GEMM (fc = act @ Wfc2^T + bfc2) ----------------
// grid (S/128, BATCH/8), block 128
__global__ void fc2_kernel(const float* __restrict__ W,
                           const float* __restrict__ bias) {
    __shared__ float sx[8][1024];
    const int b0 = blockIdx.y * 8;
    const int c  = blockIdx.x * 128 + threadIdx.x;

    float acc[8] = {0.f, 0.f, 0.f, 0.f, 0.f, 0.f, 0.f, 0.f};

    for (int kk = 0; kk < 2; kk++) {
        __syncthreads();
        for (int idx = threadIdx.x; idx < 8 * 1024; idx += 128) {
            int bb = idx >> 10, k = idx & 1023;
            sx[bb][k] = g_act[(b0 + bb) * S + kk * 1024 + k];
        }
        __syncthreads();

        const float4* Wr = (const float4*)(W + (size_t)c * S + kk * 1024);
        #pragma unroll 4
        for (int k4 = 0; k4 < 256; k4++) {
            float4 w = Wr[k4];
            #pragma unroll
            for (int bb = 0; bb < 8; bb++) {
                float4 xv = *(const float4*)&sx[bb][k4 * 4];
                acc[bb] = fmaf(w.x, xv.x, acc[bb]);
                acc[bb] = fmaf(w.y, xv.y, acc[bb]);
                acc[bb] = fmaf(w.z, xv.z, acc[bb]);
                acc[bb] = fmaf(w.w, xv.w, acc[bb]);
            }
        }
    }
    const float bc = bias[c];
    #pragma unroll
    for (int bb = 0; bb < 8; bb++) g_fc[(b0 + bb) * S + c] = acc[bb] + bc;
}

// ---------------- kernel 5: LayerNorm over last dim ----------------
// grid BATCH, block 256
__global__ void ln_kernel(const float* __restrict__ g2,
                          const float* __restrict__ b2,
                          float* __restrict__ out) {
    __shared__ float rsum[8], rsq[8];
    __shared__ float sMu, sRstd;

    const int b = blockIdx.x;
    const float* row = g_fc + b * S;
    const int tid = threadIdx.x;
    const int lane = tid & 31, wid = tid >> 5;

    float s = 0.f, s2 = 0.f;
    for (int idx = tid; idx < S; idx += 256) {
        float v = row[idx];
        s += v;
        s2 = fmaf(v, v, s2);
    }
    #pragma unroll
    for (int off = 16; off > 0; off >>= 1) {
        s  += __shfl_xor_sync(0xffffffffu, s,  off);
        s2 += __shfl_xor_sync(0xffffffffu, s2, off);
    }
    if (lane == 0) { rsum[wid] = s; rsq[wid] = s2; }
    __syncthreads();
    if (tid == 0) {
        float ts = 0.f, ts2 = 0.f;
        #pragma unroll
        for (int w = 0; w < 8; w++) { ts += rsum[w]; ts2 += rsq[w]; }
        float mu = ts * (1.0f / S);
        float var = ts2 * (1.0f / S) - mu * mu;
        sMu = mu;
        sRstd = rsqrtf(var + EPSLN);
    }
    __syncthreads();

    const float mu = sMu, rstd = sRstd;
    for (int idx = tid; idx < S; idx += 256) {
        out[b * S + idx] = (row[idx] - mu) * rstd * g2[idx] + b2[idx];
    }
}

// ---------------- launch ----------------
extern "C" void kernel_launch(void* const* d_in, const int* in_sizes, int n_in,
                              void* d_out, int out_size) {
    const float* x    = (const float*)d_in[0];
    const float* Wq   = (const float*)d_in[1];
    const float* Wk   = (const float*)d_in[2];
    const float* Wv   = (const float*)d_in[3];
    const float* p2   = (const float*)d_in[4];
    const float* Wfc2 = (const float*)d_in[5];
    const float* bfc2 = (const float*)d_in[6];
    const float* g2   = (const float*)d_in[7];
    const float* b2   = (const float*)d_in[8];
    float* out = (float*)d_out;

    zero_kernel<<<1, 32>>>();
    qkv_kernel<<<dim3(S / 128, BATCH / 8, 3), 128>>>(x, Wq, Wk, Wv);
    attn_kernel<<<dim3(BATCH, S / 256), 256>>>();
    act_kernel<<<(BATCH * S) / 256, 256>>>(p2);
    fc2_kernel<<<dim3(S / 128, BATCH / 8), 128>>>(Wfc2, bfc2);
    ln_kernel<<<BATCH, 256>>>(g2, b2, out);
}

// round 2
// speedup vs baseline: 1.8303x; 1.8303x over previous
#include <cuda_runtime.h>
#include <math.h>

#define BATCH 32
#define S 2048
#define BS (BATCH * S)
#define EPSLN 1e-5f
#define L2E 1.4426950408889634f   // log2(e)

// ---------------- scratch (no allocations allowed) ----------------
__device__ float g_qp[2 * BS];    // q partials (ksplit 2)
__device__ float g_kp[2 * BS];
__device__ float g_vp[2 * BS];
__device__ float g_num[BS];
__device__ float g_act[BS];
__device__ float g_fcp[4 * BS];   // fc2 partials (ksplit 4)
__device__ float g_Zp[BATCH * 8]; // per-(batch, attn-block) softmax denominators

__device__ __forceinline__ float ex2f(float x) {
    float y;
    asm("ex2.approx.f32 %0, %1;" : "=f"(y) : "f"(x));
    return y;
}

// ---------------- tiled GEMM block: out[b, c0+cl] += X[b, kb0:kb0+64*N] @ W[c, same k]^T ----
// 256 threads: cl = tid>>2 (64 cols), bq = tid&3 (8-batch group). 8 acc/thread.
// W staged coalesced into sW[64][68] (bank-spread), X transposed into sX[k][36].
// Register double-buffer of next chunk's global loads hides DRAM latency.
template <int NCHUNK>
__device__ __forceinline__ void gemm_block(const float* __restrict__ X,
                                           const float* __restrict__ W,
                                           float* __restrict__ out,
                                           int c0, int kb0)
{
    __shared__ float sW[64][68];
    __shared__ float sX[64][36];
    const int tid = threadIdx.x;
    const int cl = tid >> 2, bq = tid & 3;

    float acc[8];
    #pragma unroll
    for (int i = 0; i < 8; i++) acc[i] = 0.f;

    float4 wreg[4], xreg[2];
    // prefetch chunk 0
    #pragma unroll
    for (int i = 0; i < 4; i++) {
        int idx = tid + i * 256;
        wreg[i] = *(const float4*)(W + (size_t)(c0 + (idx >> 4)) * S + kb0 + (idx & 15) * 4);
    }
    #pragma unroll
    for (int i = 0; i < 2; i++) {
        int idx = tid + i * 256;
        xreg[i] = *(const float4*)(X + (size_t)(idx >> 4) * S + kb0 + (idx & 15) * 4);
    }

    for (int ch = 0; ch < NCHUNK; ch++) {
        __syncthreads();
        #pragma unroll
        for (int i = 0; i < 4; i++) {
            int idx = tid + i * 256;
            *(float4*)&sW[idx >> 4][(idx & 15) * 4] = wreg[i];
        }
        #pragma unroll
        for (int i = 0; i < 2; i++) {
            int idx = tid + i * 256;
            int b = idx >> 4, kv = (idx & 15) * 4;
            sX[kv + 0][b] = xreg[i].x;
            sX[kv + 1][b] = xreg[i].y;
            sX[kv + 2][b] = xreg[i].z;
            sX[kv + 3][b] = xreg[i].w;
        }
        __syncthreads();

        if (ch + 1 < NCHUNK) {
            const int kb = kb0 + (ch + 1) * 64;
            #pragma unroll
            for (int i = 0; i < 4; i++) {
                int idx = tid + i * 256;
                wreg[i] = *(const float4*)(W + (size_t)(c0 + (idx >> 4)) * S + kb + (idx & 15) * 4);
            }
            #pragma unroll
            for (int i = 0; i < 2; i++) {
                int idx = tid + i * 256;
                xreg[i] = *(const float4*)(X + (size_t)(idx >> 4) * S + kb + (idx & 15) * 4);
            }
        }

        #pragma unroll
        for (int k4 = 0; k4 < 16; k4++) {
            float4 wv = *(const float4*)&sW[cl][k4 * 4];
            #pragma unroll
            for (int kk = 0; kk < 4; kk++) {
                float w = (kk == 0) ? wv.x : ((kk == 1) ? wv.y : ((kk == 2) ? wv.z : wv.w));
                float4 xa = *(const float4*)&sX[k4 * 4 + kk][bq * 8];
                float4 xb = *(const float4*)&sX[k4 * 4 + kk][bq * 8 + 4];
                acc[0] = fmaf(w, xa.x, acc[0]);
                acc[1] = fmaf(w, xa.y, acc[1]);
                acc[2] = fmaf(w, xa.z, acc[2]);
                acc[3] = fmaf(w, xa.w, acc[3]);
                acc[4] = fmaf(w, xb.x, acc[4]);
                acc[5] = fmaf(w, xb.y, acc[5]);
                acc[6] = fmaf(w, xb.z, acc[6]);
                acc[7] = fmaf(w, xb.w, acc[7]);
            }
        }
    }
    const int c = c0 + cl;
    #pragma unroll
    for (int i = 0; i < 8; i++)
        out[(size_t)(bq * 8 + i) * S + c] = acc[i];
}

// ---------------- kernel 1: fused QKV GEMM, grid (32 ctiles, 2 ksplit, 3) ----------------
__global__ void __launch_bounds__(256) qkv_kernel(const float* __restrict__ x,
                                                  const float* __restrict__ Wq,
                                                  const float* __restrict__ Wk,
                                                  const float* __restrict__ Wv) {
    const int z = blockIdx.z;
    const float* W = (z == 0) ? Wq : (z == 1 ? Wk : Wv);
    float* out = ((z == 0) ? g_qp : (z == 1 ? g_kp : g_vp)) + blockIdx.y * BS;
    gemm_block<16>(x, W, out, blockIdx.x * 64, blockIdx.y * 1024);
}

// ---------------- kernel 2: attention (global softmax over outer product) ----------------
// valued[b,i] * Z_b = sum_j exp(q_i*k_j - M) * v_j ;  Z_b = sum_ij exp(q_i*k_j - M)
// grid (BATCH, 8), block 256; writes per-block Z partials (no atomics).
__global__ void attn_kernel() {
    __shared__ float sq[S], sk[S], sv[S];
    __shared__ float rqmn[8], rqmx[8], rkmn[8], rkmx[8], rsum[8];
    __shared__ float sMl2e;

    const int b = blockIdx.x;
    const float* q0 = g_qp + b * S;
    const float* q1 = g_qp + BS + b * S;
    const float* k0g = g_kp + b * S;
    const float* k1g = g_kp + BS + b * S;
    const float* v0g = g_vp + b * S;
    const float* v1g = g_vp + BS + b * S;

    const int tid = threadIdx.x;
    const int lane = tid & 31, wid = tid >> 5;

    float qmn = 3.0e38f, qmx = -3.0e38f, kmn = 3.0e38f, kmx = -3.0e38f;
    for (int idx = tid; idx < S; idx += 256) {
        float qv = q0[idx] + q1[idx];
        float kv = k0g[idx] + k1g[idx];
        sq[idx] = qv; sk[idx] = kv;
        sv[idx] = v0g[idx] + v1g[idx];
        qmn = fminf(qmn, qv); qmx = fmaxf(qmx, qv);
        kmn = fminf(kmn, kv); kmx = fmaxf(kmx, kv);
    }
    #pragma unroll
    for (int off = 16; off > 0; off >>= 1) {
        qmn = fminf(qmn, __shfl_xor_sync(0xffffffffu, qmn, off));
        qmx = fmaxf(qmx, __shfl_xor_sync(0xffffffffu, qmx, off));
        kmn = fminf(kmn, __shfl_xor_sync(0xffffffffu, kmn, off));
        kmx = fmaxf(kmx, __shfl_xor_sync(0xffffffffu, kmx, off));
    }
    if (lane == 0) { rqmn[wid] = qmn; rqmx[wid] = qmx; rkmn[wid] = kmn; rkmx[wid] = kmx; }
    __syncthreads();
    if (tid == 0) {
        float a = rqmn[0], bq = rqmx[0], cK = rkmn[0], dK = rkmx[0];
        #pragma unroll
        for (int w = 1; w < 8; w++) {
            a = fminf(a, rqmn[w]); bq = fmaxf(bq, rqmx[w]);
            cK = fminf(cK, rkmn[w]); dK = fmaxf(dK, rkmx[w]);
        }
        // max over i,j of q_i*k_j is attained at a corner (bilinear in endpoints)
        float M = fmaxf(fmaxf(a * cK, a * dK), fmaxf(bq * cK, bq * dK));
        sMl2e = M * L2E;
    }
    __syncthreads();

    const float mM = sMl2e;
    const int i = blockIdx.y * 256 + tid;
    const float qi = sq[i] * L2E;

    float num = 0.f, rs = 0.f;
    #pragma unroll 4
    for (int j4 = 0; j4 < S / 4; j4++) {
        float4 k4 = *(const float4*)&sk[j4 * 4];
        float4 v4 = *(const float4*)&sv[j4 * 4];
        float e0 = ex2f(fmaf(qi, k4.x, -mM));
        float e1 = ex2f(fmaf(qi, k4.y, -mM));
        float e2 = ex2f(fmaf(qi, k4.z, -mM));
        float e3 = ex2f(fmaf(qi, k4.w, -mM));
        num = fmaf(e0, v4.x, num); rs += e0;
        num = fmaf(e1, v4.y, num); rs += e1;
        num = fmaf(e2, v4.z, num); rs += e2;
        num = fmaf(e3, v4.w, num); rs += e3;
    }
    g_num[b * S + i] = num;

    #pragma unroll
    for (int off = 16; off > 0; off >>= 1)
        rs += __shfl_xor_sync(0xffffffffu, rs, off);
    if (lane == 0) rsum[wid] = rs;
    __syncthreads();
    if (tid == 0) {
        float tot = rsum[0];
        #pragma unroll
        for (int w = 1; w < 8; w++) tot += rsum[w];
        g_Zp[b * 8 + blockIdx.y] = tot;
    }
}

// ---------------- kernel 3: divide by Z + OptimActivation ----------------
__global__ void act_kernel(const float* __restrict__ p2) {
    const int idx = blockIdx.x * 256 + threadIdx.x;
    const int b = idx >> 11;

    float Z = 0.f;
    #pragma unroll
    for (int pz = 0; pz < 8; pz++) Z += g_Zp[b * 8 + pz];

    // softmax over 5 activation params
    float p[5];
    #pragma unroll
    for (int t = 0; t < 5; t++) p[t] = p2[t];
    float pm = p[0];
    #pragma unroll
    for (int t = 1; t < 5; t++) pm = fmaxf(pm, p[t]);
    float pe[5], psum = 0.f;
    #pragma unroll
    for (int t = 0; t < 5; t++) { pe[t] = ex2f((p[t] - pm) * L2E); psum += pe[t]; }
    const float inv = __fdividef(1.0f, psum);
    const float ps0 = pe[0] * inv, ps1 = pe[1] * inv, ps2 = pe[2] * inv;

    const float val = __fdividef(g_num[idx], Z);
    const float sig = __fdividef(1.0f, 1.0f + ex2f(-val * L2E));
    g_act[idx] = sig * val * ps0 + __sinf(val) * ps1 + val * ps2;
}

// ---------------- kernel 4: fc2 GEMM, grid (32 ctiles, 4 ksplit) ----------------
__global__ void __launch_bounds__(256) fc2_kernel(const float* __restrict__ W) {
    gemm_block<8>(g_act, W, g_fcp + blockIdx.y * BS, blockIdx.x * 64, blockIdx.y * 512);
}

// ---------------- kernel 5: combine fc2 partials + bias + LayerNorm ----------------
// grid BATCH, block 512
__global__ void ln_kernel(const float* __restrict__ bias,
                          const float* __restrict__ g2,
                          const float* __restrict__ b2,
                          float* __restrict__ out) {
    __shared__ float sRow[S];
    __shared__ float rsum[16], rsq[16];
    __shared__ float sMu, sRstd;

    const int b = blockIdx.x;
    const int tid = threadIdx.x;
    const int lane = tid & 31, wid = tid >> 5;

    float s = 0.f, s2 = 0.f;
    #pragma unroll
    for (int it = 0; it < 4; it++) {
        int idx = tid + it * 512;
        float v = g_fcp[b * S + idx] + g_fcp[BS + b * S + idx]
                + g_fcp[2 * BS + b * S + idx] + g_fcp[3 * BS + b * S + idx]
                + bias[idx];
        sRow[idx] = v;
        s += v;
        s2 = fmaf(v, v, s2);
    }
    #pragma unroll
    for (int off = 16; off > 0; off >>= 1) {
        s  += __shfl_xor_sync(0xffffffffu, s,  off);
        s2 += __shfl_xor_sync(0xffffffffu, s2, off);
    }
    if (lane == 0) { rsum[wid] = s; rsq[wid] = s2; }
    __syncthreads();
    if (tid == 0) {
        float ts = 0.f, ts2 = 0.f;
        #pragma unroll
        for (int w = 0; w < 16; w++) { ts += rsum[w]; ts2 += rsq[w]; }
        float mu = ts * (1.0f / S);
        float var = ts2 * (1.0f / S) - mu * mu;
        sMu = mu;
        sRstd = rsqrtf(var + EPSLN);
    }
    __syncthreads();

    const float mu = sMu, rstd = sRstd;
    #pragma unroll
    for (int it = 0; it < 4; it++) {
        int idx = tid + it * 512;
        out[b * S + idx] = (sRow[idx] - mu) * rstd * g2[idx] + b2[idx];
    }
}

// ---------------- launch ----------------
extern "C" void kernel_launch(void* const* d_in, const int* in_sizes, int n_in,
                              void* d_out, int out_size) {
    const float* x    = (const float*)d_in[0];
    const float* Wq   = (const float*)d_in[1];
    const float* Wk   = (const float*)d_in[2];
    const float* Wv   = (const float*)d_in[3];
    const float* p2   = (const float*)d_in[4];
    const float* Wfc2 = (const float*)d_in[5];
    const float* bfc2 = (const float*)d_in[6];
    const float* g2   = (const float*)d_in[7];
    const float* b2   = (const float*)d_in[8];
    float* out = (float*)d_out;

    qkv_kernel<<<dim3(32, 2, 3), 256>>>(x, Wq, Wk, Wv);
    attn_kernel<<<dim3(BATCH, 8), 256>>>();
    act_kernel<<<BS / 256, 256>>>(p2);
    fc2_kernel<<<dim3(32, 4), 256>>>(Wfc2);
    ln_kernel<<<BATCH, 512>>>(bfc2, g2, b2, out);
}

// round 5
// speedup vs baseline: 2.9080x; 1.5888x over previous
#include <cuda_runtime.h>
#include <math.h>

#define BATCH 32
#define S 2048
#define BS (BATCH * S)
#define EPSLN 1e-5f
#define L2E 1.4426950408889634f   // log2(e)

#define QKV_KSPLIT 4
#define FC2_KSPLIT 8

// ---------------- scratch (no allocations allowed) ----------------
__device__ float g_qp[QKV_KSPLIT * BS];
__device__ float g_kp[QKV_KSPLIT * BS];
__device__ float g_vp[QKV_KSPLIT * BS];
__device__ float g_num[BS];
__device__ float g_act[BS];
__device__ float g_fcp[FC2_KSPLIT * BS];
__device__ float g_Zp[BATCH * 8];

__device__ __forceinline__ float ex2f(float x) {
    float y;
    asm("ex2.approx.f32 %0, %1;" : "=f"(y) : "f"(x));
    return y;
}

__device__ __forceinline__ void cp_async16(unsigned dst, const void* src) {
    asm volatile("cp.async.cg.shared.global [%0], [%1], 16;" :: "r"(dst), "l"(src));
}
__device__ __forceinline__ void cp_commit() {
    asm volatile("cp.async.commit_group;");
}

__device__ __forceinline__ float fcomp(float4 v, int k) {
    return (k == 0) ? v.x : ((k == 1) ? v.y : ((k == 2) ? v.z : v.w));
}

// ---------------- tiled GEMM: out[b, c0+lc] = X[32, K-range] @ W[c, k]^T ----------------
// Block: 256 threads, tile 32 batch x 128 cols, K-chunk 32.
// Thread tile: 4 cols x 4 batches (16 acc). cg=tid>>3 (32 col-groups), bg=tid&7 (8 b-groups).
// W: cp.async.cg 2-stage double buffer. Swizzle key = (r>>2)&7 so the 4 per-thread read
//    rows {i,4+i,8+i,12+i} hit 4 distinct bank quads (conflict-free LDS.128).
// Pipeline order (race-free): wait_group 0 -> barrier -> issue next stage -> sX -> barrier -> compute.
template <int NCHUNK>
__device__ __forceinline__ void gemm_block(const float* __restrict__ X,
                                           const float* __restrict__ W,
                                           float* __restrict__ out,
                                           int c0, int kb0)
{
    __shared__ __align__(16) float sW[2][128 * 32];
    __shared__ __align__(16) float sX[32][36];

    const int tid = threadIdx.x;
    const int cg = tid >> 3;       // 0..31 -> cols lc0..lc0+3
    const int bg = tid & 7;        // 0..7  -> batches bg*4..bg*4+3
    const int lc0 = cg * 4;

    const unsigned swbase = (unsigned)__cvta_generic_to_shared(&sW[0][0]);

    const int wr  = tid >> 3;      // rows wr, wr+32, wr+64, wr+96
    const int wk4 = tid & 7;
    const int xb  = tid >> 3;
    const int xk4 = tid & 7;

    float acc[4][4];
    #pragma unroll
    for (int i = 0; i < 4; i++)
        #pragma unroll
        for (int j = 0; j < 4; j++) acc[i][j] = 0.f;

    // ---- prologue: W stage 0 + X chunk 0 ----
    #pragma unroll
    for (int i = 0; i < 4; i++) {
        int r = wr + i * 32;
        unsigned dst = swbase + (unsigned)((r * 32 + ((wk4 ^ ((r >> 2) & 7)) * 4)) * 4);
        cp_async16(dst, W + (size_t)(c0 + r) * S + kb0 + wk4 * 4);
    }
    cp_commit();
    float4 xreg = *(const float4*)(X + (size_t)xb * S + kb0 + xk4 * 4);

    for (int ch = 0; ch < NCHUNK; ch++) {
        asm volatile("cp.async.wait_group 0;");
        __syncthreads();   // all threads done with prev compute; W stage ch visible to all

        if (ch + 1 < NCHUNK) {
            const int kb = kb0 + (ch + 1) * 32;
            const int nst = (ch + 1) & 1;
            #pragma unroll
            for (int i = 0; i < 4; i++) {
                int r = wr + i * 32;
                unsigned dst = swbase + (unsigned)((nst * 4096 + r * 32 + ((wk4 ^ ((r >> 2) & 7)) * 4)) * 4);
                cp_async16(dst, W + (size_t)(c0 + r) * S + kb + wk4 * 4);
            }
            cp_commit();
        }

        sX[xk4 * 4 + 0][xb] = xreg.x;
        sX[xk4 * 4 + 1][xb] = xreg.y;
        sX[xk4 * 4 + 2][xb] = xreg.z;
        sX[xk4 * 4 + 3][xb] = xreg.w;
        if (ch + 1 < NCHUNK)
            xreg = *(const float4*)(X + (size_t)xb * S + kb0 + (ch + 1) * 32 + xk4 * 4);
        __syncthreads();

        const float* wst = &sW[ch & 1][0];
        #pragma unroll
        for (int k4 = 0; k4 < 8; k4++) {
            float4 w4[4];
            #pragma unroll
            for (int i = 0; i < 4; i++) {
                int lc = lc0 + i;
                w4[i] = *(const float4*)&wst[lc * 32 + ((k4 ^ ((lc >> 2) & 7)) * 4)];
            }
            #pragma unroll
            for (int kk = 0; kk < 4; kk++) {
                float4 xv = *(const float4*)&sX[k4 * 4 + kk][bg * 4];
                #pragma unroll
                for (int i = 0; i < 4; i++) {
                    float w = fcomp(w4[i], kk);
                    acc[i][0] = fmaf(w, xv.x, acc[i][0]);
                    acc[i][1] = fmaf(w, xv.y, acc[i][1]);
                    acc[i][2] = fmaf(w, xv.z, acc[i][2]);
                    acc[i][3] = fmaf(w, xv.w, acc[i][3]);
                }
            }
        }
    }

    #pragma unroll
    for (int j = 0; j < 4; j++) {
        const int b = bg * 4 + j;
        #pragma unroll
        for (int i = 0; i < 4; i++)
            out[(size_t)b * S + c0 + lc0 + i] = acc[i][j];
    }
}

// ---------------- kernel 1: fused QKV GEMM, grid (16 ctiles, 4 ksplit, 3) ----------------
__global__ void __launch_bounds__(256) qkv_kernel(const float* __restrict__ x,
                                                  const float* __restrict__ Wq,
                                                  const float* __restrict__ Wk,
                                                  const float* __restrict__ Wv) {
    const int z = blockIdx.z;
    const float* W = (z == 0) ? Wq : (z == 1 ? Wk : Wv);
    float* out = ((z == 0) ? g_qp : (z == 1 ? g_kp : g_vp)) + (size_t)blockIdx.y * BS;
    gemm_block<16>(x, W, out, blockIdx.x * 128, blockIdx.y * (S / QKV_KSPLIT));
}

// ---------------- kernel 2: attention (global softmax over outer product) ----------------
// valued[b,i] * Z_b = sum_j exp(q_i*k_j - M) * v_j ;  Z_b = sum_ij exp(q_i*k_j - M)
// grid (BATCH, 8), block 256; combines qkv ksplit partials on load.
__global__ void attn_kernel() {
    __shared__ float sq[S], sk[S], sv[S];
    __shared__ float rqmn[8], rqmx[8], rkmn[8], rkmx[8], rsum[8];
    __shared__ float sMl2e;

    const int b = blockIdx.x;
    const int tid = threadIdx.x;
    const int lane = tid & 31, wid = tid >> 5;

    float qmn = 3.0e38f, qmx = -3.0e38f, kmn = 3.0e38f, kmx = -3.0e38f;
    for (int idx = tid; idx < S; idx += 256) {
        float qv = 0.f, kv = 0.f, vv = 0.f;
        #pragma unroll
        for (int p = 0; p < QKV_KSPLIT; p++) {
            qv += g_qp[(size_t)p * BS + b * S + idx];
            kv += g_kp[(size_t)p * BS + b * S + idx];
            vv += g_vp[(size_t)p * BS + b * S + idx];
        }
        sq[idx] = qv; sk[idx] = kv; sv[idx] = vv;
        qmn = fminf(qmn, qv); qmx = fmaxf(qmx, qv);
        kmn = fminf(kmn, kv); kmx = fmaxf(kmx, kv);
    }
    #pragma unroll
    for (int off = 16; off > 0; off >>= 1) {
        qmn = fminf(qmn, __shfl_xor_sync(0xffffffffu, qmn, off));
        qmx = fmaxf(qmx, __shfl_xor_sync(0xffffffffu, qmx, off));
        kmn = fminf(kmn, __shfl_xor_sync(0xffffffffu, kmn, off));
        kmx = fmaxf(kmx, __shfl_xor_sync(0xffffffffu, kmx, off));
    }
    if (lane == 0) { rqmn[wid] = qmn; rqmx[wid] = qmx; rkmn[wid] = kmn; rkmx[wid] = kmx; }
    __syncthreads();
    if (tid == 0) {
        float a = rqmn[0], bq = rqmx[0], cK = rkmn[0], dK = rkmx[0];
        #pragma unroll
        for (int w = 1; w < 8; w++) {
            a = fminf(a, rqmn[w]); bq = fmaxf(bq, rqmx[w]);
            cK = fminf(cK, rkmn[w]); dK = fmaxf(dK, rkmx[w]);
        }
        // max over i,j of q_i*k_j is at a corner (bilinear in endpoints)
        float M = fmaxf(fmaxf(a * cK, a * dK), fmaxf(bq * cK, bq * dK));
        sMl2e = M * L2E;
    }
    __syncthreads();

    const float mM = sMl2e;
    const int i = blockIdx.y * 256 + tid;
    const float qi = sq[i] * L2E;

    float num = 0.f, rs = 0.f;
    #pragma unroll 4
    for (int j4 = 0; j4 < S / 4; j4++) {
        float4 k4 = *(const float4*)&sk[j4 * 4];
        float4 v4 = *(const float4*)&sv[j4 * 4];
        float e0 = ex2f(fmaf(qi, k4.x, -mM));
        float e1 = ex2f(fmaf(qi, k4.y, -mM));
        float e2 = ex2f(fmaf(qi, k4.z, -mM));
        float e3 = ex2f(fmaf(qi, k4.w, -mM));
        num = fmaf(e0, v4.x, num); rs += e0;
        num = fmaf(e1, v4.y, num); rs += e1;
        num = fmaf(e2, v4.z, num); rs += e2;
        num = fmaf(e3, v4.w, num); rs += e3;
    }
    g_num[b * S + i] = num;

    #pragma unroll
    for (int off = 16; off > 0; off >>= 1)
        rs += __shfl_xor_sync(0xffffffffu, rs, off);
    if (lane == 0) rsum[wid] = rs;
    __syncthreads();
    if (tid == 0) {
        float tot = rsum[0];
        #pragma unroll
        for (int w = 1; w < 8; w++) tot += rsum[w];
        g_Zp[b * 8 + blockIdx.y] = tot;
    }
}

// ---------------- kernel 3: divide by Z + OptimActivation ----------------
__global__ void act_kernel(const float* __restrict__ p2) {
    const int idx = blockIdx.x * 256 + threadIdx.x;
    const int b = idx >> 11;

    float Z = 0.f;
    #pragma unroll
    for (int pz = 0; pz < 8; pz++) Z += g_Zp[b * 8 + pz];

    float p[5];
    #pragma unroll
    for (int t = 0; t < 5; t++) p[t] = p2[t];
    float pm = p[0];
    #pragma unroll
    for (int t = 1; t < 5; t++) pm = fmaxf(pm, p[t]);
    float pe[5], psum = 0.f;
    #pragma unroll
    for (int t = 0; t < 5; t++) { pe[t] = ex2f((p[t] - pm) * L2E); psum += pe[t]; }
    const float inv = __fdividef(1.0f, psum);
    const float ps0 = pe[0] * inv, ps1 = pe[1] * inv, ps2 = pe[2] * inv;

    const float val = __fdividef(g_num[idx], Z);
    const float sig = __fdividef(1.0f, 1.0f + ex2f(-val * L2E));
    g_act[idx] = sig * val * ps0 + __sinf(val) * ps1 + val * ps2;
}

// ---------------- kernel 4: fc2 GEMM, grid (16 ctiles, 8 ksplit) ----------------
__global__ void __launch_bounds__(256) fc2_kernel(const float* __restrict__ W) {
    gemm_block<8>(g_act, W, g_fcp + (size_t)blockIdx.y * BS,
                  blockIdx.x * 128, blockIdx.y * (S / FC2_KSPLIT));
}

// ---------------- kernel 5: combine fc2 partials + bias + LayerNorm ----------------
// grid BATCH, block 512
__global__ void ln_kernel(const float* __restrict__ bias,
                          const float* __restrict__ g2,
                          const float* __restrict__ b2,
                          float* __restrict__ out) {
    __shared__ float sRow[S];
    __shared__ float rsum[16], rsq[16];
    __shared__ float sMu, sRstd;

    const int b = blockIdx.x;
    const int tid = threadIdx.x;
    const int lane = tid & 31, wid = tid >> 5;

    float s = 0.f, s2 = 0.f;
    #pragma unroll
    for (int it = 0; it < 4; it++) {
        int idx = tid + it * 512;
        float v = bias[idx];
        #pragma unroll
        for (int p = 0; p < FC2_KSPLIT; p++)
            v += g_fcp[(size_t)p * BS + b * S + idx];
        sRow[idx] = v;
        s += v;
        s2 = fmaf(v, v, s2);
    }
    #pragma unroll
    for (int off = 16; off > 0; off >>= 1) {
        s  += __shfl_xor_sync(0xffffffffu, s,  off);
        s2 += __shfl_xor_sync(0xffffffffu, s2, off);
    }
    if (lane == 0) { rsum[wid] = s; rsq[wid] = s2; }
    __syncthreads();
    if (tid == 0) {
        float ts = 0.f, ts2 = 0.f;
        #pragma unroll
        for (int w = 0; w < 16; w++) { ts += rsum[w]; ts2 += rsq[w]; }
        float mu = ts * (1.0f / S);
        float var = ts2 * (1.0f / S) - mu * mu;
        sMu = mu;
        sRstd = rsqrtf(var + EPSLN);
    }
    __syncthreads();

    const float mu = sMu, rstd = sRstd;
    #pragma unroll
    for (int it = 0; it < 4; it++) {
        int idx = tid + it * 512;
        out[b * S + idx] = (sRow[idx] - mu) * rstd * g2[idx] + b2[idx];
    }
}

// ---------------- launch ----------------
extern "C" void kernel_launch(void* const* d_in, const int* in_sizes, int n_in,
                              void* d_out, int out_size) {
    const float* x    = (const float*)d_in[0];
    const float* Wq   = (const float*)d_in[1];
    const float* Wk   = (const float*)d_in[2];
    const float* Wv   = (const float*)d_in[3];
    const float* p2   = (const float*)d_in[4];
    const float* Wfc2 = (const float*)d_in[5];
    const float* bfc2 = (const float*)d_in[6];
    const float* g2   = (const float*)d_in[7];
    const float* b2   = (const float*)d_in[8];
    float* out = (float*)d_out;

    qkv_kernel<<<dim3(16, QKV_KSPLIT, 3), 256>>>(x, Wq, Wk, Wv);
    attn_kernel<<<dim3(BATCH, 8), 256>>>();
    act_kernel<<<BS / 256, 256>>>(p2);
    fc2_kernel<<<dim3(16, FC2_KSPLIT), 256>>>(Wfc2);
    ln_kernel<<<BATCH, 512>>>(bfc2, g2, b2, out);
}

// round 9
// speedup vs baseline: 2.9840x; 1.0261x over previous
#include <cuda_runtime.h>
#include <math.h>
#include <stdint.h>

#define BATCH 32
#define S 2048
#define BS (BATCH * S)
#define EPSLN 1e-5f
#define L2E 1.4426950408889634f   // log2(e)

#define QKV_KSPLIT 8
#define FC2_KSPLIT 8

// ---------------- scratch (no allocations allowed) ----------------
__device__ float g_qp[QKV_KSPLIT * BS];
__device__ float g_kp[QKV_KSPLIT * BS];
__device__ float g_vp[QKV_KSPLIT * BS];
__device__ float g_qc[BS];
__device__ float g_kc[BS];
__device__ float g_vc[BS];
__device__ float g_num[BS];
__device__ float g_act[BS];
__device__ float g_fcp[FC2_KSPLIT * BS];
__device__ float g_Zp[BATCH * 8];

__device__ __forceinline__ float ex2f(float x) {
    float y;
    asm("ex2.approx.f32 %0, %1;" : "=f"(y) : "f"(x));
    return y;
}

__device__ __forceinline__ float cvt_tf32(float x) {
    uint32_t u;
    asm("cvt.rna.tf32.f32 %0, %1;" : "=r"(u) : "f"(x));
    return __uint_as_float(u);
}

__device__ __forceinline__ void mma_tf32(float acc[4],
                                         uint32_t a0, uint32_t a1, uint32_t a2, uint32_t a3,
                                         uint32_t b0, uint32_t b1) {
    asm volatile("mma.sync.aligned.m16n8k8.row.col.f32.tf32.tf32.f32 "
                 "{%0,%1,%2,%3}, {%4,%5,%6,%7}, {%8,%9}, {%0,%1,%2,%3};"
                 : "+f"(acc[0]), "+f"(acc[1]), "+f"(acc[2]), "+f"(acc[3])
                 : "r"(a0), "r"(a1), "r"(a2), "r"(a3), "r"(b0), "r"(b1));
}

__device__ __forceinline__ float f4c(float4 v, int k) {
    return (k == 0) ? v.x : ((k == 1) ? v.y : ((k == 2) ? v.z : v.w));
}

// SMEM geometry: panels with fragment-permuted k layout pos(k) = (k%8)*4 + k/8,
// row stride 48 floats (12 quads == 4 mod 8 -> conflict-free frag LDS.128).
#define PSTRIDE 48
#define SM_A_HI 0
#define SM_A_LO (32 * PSTRIDE)
#define SM_B_HI (64 * PSTRIDE)
#define SM_B_LO (192 * PSTRIDE)
#define SMEM_FLOATS (320 * PSTRIDE)
#define SMEM_BYTES (SMEM_FLOATS * 4)

// ---------------- tensor-core GEMM: out[b, c0+*] = X[32, kslice] @ W[c, kslice]^T ----------
// 256 thr / 8 warps; block tile 32x128, K-chunk 32; 3xTF32 (hihi + hilo + lohi).
// Warp w: m-half = w&1, n-group = w>>1 (4 n8-tiles). Reg prefetch of next chunk.
template <int NCHUNK>
__device__ __forceinline__ void gemm_mma(const float* __restrict__ X,
                                         const float* __restrict__ W,
                                         float* __restrict__ out,
                                         int c0, int kb0)
{
    extern __shared__ float sm[];
    float* sAhi = sm + SM_A_HI;
    float* sAlo = sm + SM_A_LO;
    float* sBhi = sm + SM_B_HI;
    float* sBlo = sm + SM_B_LO;

    const int tid = threadIdx.x;
    const int L = tid & 31, w = tid >> 5;
    const int mh = w & 1, ng = w >> 1;

    float acc[4][4];
    #pragma unroll
    for (int i = 0; i < 4; i++)
        #pragma unroll
        for (int j = 0; j < 4; j++) acc[i][j] = 0.f;

    // loader: warp w covers W cols {w+8i}, X rows {w+8i}; lane = k
    const int posL = ((L & 7) << 2) + (L >> 3);

    float wreg[16], xreg[4];
    #pragma unroll
    for (int i = 0; i < 16; i++)
        wreg[i] = W[(size_t)(c0 + w + 8 * i) * S + kb0 + L];
    #pragma unroll
    for (int i = 0; i < 4; i++)
        xreg[i] = X[(size_t)(w + 8 * i) * S + kb0 + L];

    for (int ch = 0; ch < NCHUNK; ch++) {
        __syncthreads();   // previous compute finished; smem free to overwrite
        #pragma unroll
        for (int i = 0; i < 16; i++) {
            float v = wreg[i];
            float hi = cvt_tf32(v);
            float lo = cvt_tf32(v - hi);
            sBhi[(w + 8 * i) * PSTRIDE + posL] = hi;
            sBlo[(w + 8 * i) * PSTRIDE + posL] = lo;
        }
        #pragma unroll
        for (int i = 0; i < 4; i++) {
            float v = xreg[i];
            float hi = cvt_tf32(v);
            float lo = cvt_tf32(v - hi);
            sAhi[(w + 8 * i) * PSTRIDE + posL] = hi;
            sAlo[(w + 8 * i) * PSTRIDE + posL] = lo;
        }
        __syncthreads();

        if (ch + 1 < NCHUNK) {
            const int k0 = kb0 + (ch + 1) * 32;
            #pragma unroll
            for (int i = 0; i < 16; i++)
                wreg[i] = W[(size_t)(c0 + w + 8 * i) * S + k0 + L];
            #pragma unroll
            for (int i = 0; i < 4; i++)
                xreg[i] = X[(size_t)(w + 8 * i) * S + k0 + L];
        }

        // A fragments for all 4 k8-steps of this chunk (LDS.128 each)
        const int rA = mh * 16 + (L >> 2);
        const int ca = L & 3;
        float4 Ah0 = *(const float4*)&sAhi[rA * PSTRIDE + ca * 4];
        float4 Ah1 = *(const float4*)&sAhi[(rA + 8) * PSTRIDE + ca * 4];
        float4 Ah2 = *(const float4*)&sAhi[rA * PSTRIDE + (ca + 4) * 4];
        float4 Ah3 = *(const float4*)&sAhi[(rA + 8) * PSTRIDE + (ca + 4) * 4];
        float4 Al0 = *(const float4*)&sAlo[rA * PSTRIDE + ca * 4];
        float4 Al1 = *(const float4*)&sAlo[(rA + 8) * PSTRIDE + ca * 4];
        float4 Al2 = *(const float4*)&sAlo[rA * PSTRIDE + (ca + 4) * 4];
        float4 Al3 = *(const float4*)&sAlo[(rA + 8) * PSTRIDE + (ca + 4) * 4];

        #pragma unroll
        for (int nt = 0; nt < 4; nt++) {
            const int nc = (ng * 32 + nt * 8 + (L >> 2)) * PSTRIDE;
            float4 Bh0 = *(const float4*)&sBhi[nc + ca * 4];
            float4 Bh1 = *(const float4*)&sBhi[nc + (ca + 4) * 4];
            float4 Bl0 = *(const float4*)&sBlo[nc + ca * 4];
            float4 Bl1 = *(const float4*)&sBlo[nc + (ca + 4) * 4];
            #pragma unroll
            for (int s = 0; s < 4; s++) {
                uint32_t a0h = __float_as_uint(f4c(Ah0, s));
                uint32_t a1h = __float_as_uint(f4c(Ah1, s));
                uint32_t a2h = __float_as_uint(f4c(Ah2, s));
                uint32_t a3h = __float_as_uint(f4c(Ah3, s));
                uint32_t b0h = __float_as_uint(f4c(Bh0, s));
                uint32_t b1h = __float_as_uint(f4c(Bh1, s));
                mma_tf32(acc[nt], a0h, a1h, a2h, a3h, b0h, b1h);             // hi*hi
                mma_tf32(acc[nt], a0h, a1h, a2h, a3h,
                         __float_as_uint(f4c(Bl0, s)), __float_as_uint(f4c(Bl1, s)));  // hi*lo
                mma_tf32(acc[nt],
                         __float_as_uint(f4c(Al0, s)), __float_as_uint(f4c(Al1, s)),
                         __float_as_uint(f4c(Al2, s)), __float_as_uint(f4c(Al3, s)),
                         b0h, b1h);                                          // lo*hi
            }
        }
    }

    const int rowO = mh * 16 + (L >> 2);
    #pragma unroll
    for (int nt = 0; nt < 4; nt++) {
        const int colO = c0 + ng * 32 + nt * 8 + 2 * (L & 3);
        *(float2*)&out[(size_t)rowO * S + colO] = make_float2(acc[nt][0], acc[nt][1]);
        *(float2*)&out[(size_t)(rowO + 8) * S + colO] = make_float2(acc[nt][2], acc[nt][3]);
    }
}

// ---------------- kernel 1: fused QKV GEMM, grid (16 ctiles, 8 ksplit, 3) ----------------
__global__ void __launch_bounds__(256, 2) qkv_kernel(const float* __restrict__ x,
                                                     const float* __restrict__ Wq,
                                                     const float* __restrict__ Wk,
                                                     const float* __restrict__ Wv) {
    const int z = blockIdx.z;
    const float* W = (z == 0) ? Wq : (z == 1 ? Wk : Wv);
    float* out = ((z == 0) ? g_qp : (z == 1 ? g_kp : g_vp)) + (size_t)blockIdx.y * BS;
    gemm_mma<64 / QKV_KSPLIT>(x, W, out, blockIdx.x * 128,
                              blockIdx.y * (S / QKV_KSPLIT));
}

// ---------------- kernel 1b: combine qkv partials ----------------
__global__ void combine_kernel() {
    const int idx = blockIdx.x * 256 + threadIdx.x;
    float q = 0.f, k = 0.f, v = 0.f;
    #pragma unroll
    for (int p = 0; p < QKV_KSPLIT; p++) {
        q += g_qp[(size_t)p * BS + idx];
        k += g_kp[(size_t)p * BS + idx];
        v += g_vp[(size_t)p * BS + idx];
    }
    g_qc[idx] = q; g_kc[idx] = k; g_vc[idx] = v;
}

// ---------------- kernel 2: attention (global softmax over outer product) ----------------
// valued[b,i] * Z_b = sum_j exp(q_i*k_j - M) * v_j ;  Z_b = sum_ij exp(q_i*k_j - M)
__global__ void attn_kernel() {
    __shared__ float sq[S], sk[S], sv[S];
    __shared__ float rqmn[8], rqmx[8], rkmn[8], rkmx[8], rsum[8];
    __shared__ float sMl2e;

    const int b = blockIdx.x;
    const int tid = threadIdx.x;
    const int lane = tid & 31, wid = tid >> 5;

    float qmn = 3.0e38f, qmx = -3.0e38f, kmn = 3.0e38f, kmx = -3.0e38f;
    for (int idx = tid; idx < S; idx += 256) {
        float qv = g_qc[b * S + idx];
        float kv = g_kc[b * S + idx];
        sq[idx] = qv; sk[idx] = kv; sv[idx] = g_vc[b * S + idx];
        qmn = fminf(qmn, qv); qmx = fmaxf(qmx, qv);
        kmn = fminf(kmn, kv); kmx = fmaxf(kmx, kv);
    }
    #pragma unroll
    for (int off = 16; off > 0; off >>= 1) {
        qmn = fminf(qmn, __shfl_xor_sync(0xffffffffu, qmn, off));
        qmx = fmaxf(qmx, __shfl_xor_sync(0xffffffffu, qmx, off));
        kmn = fminf(kmn, __shfl_xor_sync(0xffffffffu, kmn, off));
        kmx = fmaxf(kmx, __shfl_xor_sync(0xffffffffu, kmx, off));
    }
    if (lane == 0) { rqmn[wid] = qmn; rqmx[wid] = qmx; rkmn[wid] = kmn; rkmx[wid] = kmx; }
    __syncthreads();
    if (tid == 0) {
        float a = rqmn[0], bq = rqmx[0], cK = rkmn[0], dK = rkmx[0];
        #pragma unroll
        for (int w = 1; w < 8; w++) {
            a = fminf(a, rqmn[w]); bq = fmaxf(bq, rqmx[w]);
            cK = fminf(cK, rkmn[w]); dK = fmaxf(dK, rkmx[w]);
        }
        // max over i,j of q_i*k_j is at a corner (bilinear in endpoints)
        float M = fmaxf(fmaxf(a * cK, a * dK), fmaxf(bq * cK, bq * dK));
        sMl2e = M * L2E;
    }
    __syncthreads();

    const float mM = sMl2e;
    const int i = blockIdx.y * 256 + tid;
    const float qi = sq[i] * L2E;

    float num = 0.f, rs = 0.f;
    #pragma unroll 4
    for (int j4 = 0; j4 < S / 4; j4++) {
        float4 k4 = *(const float4*)&sk[j4 * 4];
        float4 v4 = *(const float4*)&sv[j4 * 4];
        float e0 = ex2f(fmaf(qi, k4.x, -mM));
        float e1 = ex2f(fmaf(qi, k4.y, -mM));
        float e2 = ex2f(fmaf(qi, k4.z, -mM));
        float e3 = ex2f(fmaf(qi, k4.w, -mM));
        num = fmaf(e0, v4.x, num); rs += e0;
        num = fmaf(e1, v4.y, num); rs += e1;
        num = fmaf(e2, v4.z, num); rs += e2;
        num = fmaf(e3, v4.w, num); rs += e3;
    }
    g_num[b * S + i] = num;

    #pragma unroll
    for (int off = 16; off > 0; off >>= 1)
        rs += __shfl_xor_sync(0xffffffffu, rs, off);
    if (lane == 0) rsum[wid] = rs;
    __syncthreads();
    if (tid == 0) {
        float tot = rsum[0];
        #pragma unroll
        for (int w = 1; w < 8; w++) tot += rsum[w];
        g_Zp[b * 8 + blockIdx.y] = tot;
    }
}

// ---------------- kernel 3: divide by Z + OptimActivation ----------------
__global__ void act_kernel(const float* __restrict__ p2) {
    const int idx = blockIdx.x * 256 + threadIdx.x;
    const int b = idx >> 11;

    float Z = 0.f;
    #pragma unroll
    for (int pz = 0; pz < 8; pz++) Z += g_Zp[b * 8 + pz];

    float p[5];
    #pragma unroll
    for (int t = 0; t < 5; t++) p[t] = p2[t];
    float pm = p[0];
    #pragma unroll
    for (int t = 1; t < 5; t++) pm = fmaxf(pm, p[t]);
    float pe[5], psum = 0.f;
    #pragma unroll
    for (int t = 0; t < 5; t++) { pe[t] = ex2f((p[t] - pm) * L2E); psum += pe[t]; }
    const float inv = __fdividef(1.0f, psum);
    const float ps0 = pe[0] * inv, ps1 = pe[1] * inv, ps2 = pe[2] * inv;

    const float val = __fdividef(g_num[idx], Z);
    const float sig = __fdividef(1.0f, 1.0f + ex2f(-val * L2E));
    g_act[idx] = sig * val * ps0 + __sinf(val) * ps1 + val * ps2;
}

// ---------------- kernel 4: fc2 GEMM, grid (16 ctiles, 8 ksplit) ----------------
__global__ void __launch_bounds__(256, 2) fc2_kernel(const float* __restrict__ W) {
    gemm_mma<64 / FC2_KSPLIT>(g_act, W, g_fcp + (size_t)blockIdx.y * BS,
                              blockIdx.x * 128, blockIdx.y * (S / FC2_KSPLIT));
}

// ---------------- kernel 5: combine fc2 partials + bias + LayerNorm ----------------
__global__ void ln_kernel(const float* __restrict__ bias,
                          const float* __restrict__ g2,
                          const float* __restrict__ b2,
                          float* __restrict__ out) {
    __shared__ float sRow[S];
    __shared__ float rsum[16], rsq[16];
    __shared__ float sMu, sRstd;

    const int b = blockIdx.x;
    const int tid = threadIdx.x;
    const int lane = tid & 31, wid = tid >> 5;

    float s = 0.f, s2 = 0.f;
    #pragma unroll
    for (int it = 0; it < 4; it++) {
        int idx = tid + it * 512;
        float v = bias[idx];
        #pragma unroll
        for (int p = 0; p < FC2_KSPLIT; p++)
            v += g_fcp[(size_t)p * BS + b * S + idx];
        sRow[idx] = v;
        s += v;
        s2 = fmaf(v, v, s2);
    }
    #pragma unroll
    for (int off = 16; off > 0; off >>= 1) {
        s  += __shfl_xor_sync(0xffffffffu, s,  off);
        s2 += __shfl_xor_sync(0xffffffffu, s2, off);
    }
    if (lane == 0) { rsum[wid] = s; rsq[wid] = s2; }
    __syncthreads();
    if (tid == 0) {
        float ts = 0.f, ts2 = 0.f;
        #pragma unroll
        for (int w = 0; w < 16; w++) { ts += rsum[w]; ts2 += rsq[w]; }
        float mu = ts * (1.0f / S);
        float var = ts2 * (1.0f / S) - mu * mu;
        sMu = mu;
        sRstd = rsqrtf(var + EPSLN);
    }
    __syncthreads();

    const float mu = sMu, rstd = sRstd;
    #pragma unroll
    for (int it = 0; it < 4; it++) {
        int idx = tid + it * 512;
        out[b * S + idx] = (sRow[idx] - mu) * rstd * g2[idx] + b2[idx];
    }
}

// ---------------- launch ----------------
extern "C" void kernel_launch(void* const* d_in, const int* in_sizes, int n_in,
                              void* d_out, int out_size) {
    const float* x    = (const float*)d_in[0];
    const float* Wq   = (const float*)d_in[1];
    const float* Wk   = (const float*)d_in[2];
    const float* Wv   = (const float*)d_in[3];
    const float* p2   = (const float*)d_in[4];
    const float* Wfc2 = (const float*)d_in[5];
    const float* bfc2 = (const float*)d_in[6];
    const float* g2   = (const float*)d_in[7];
    const float* b2   = (const float*)d_in[8];
    float* out = (float*)d_out;

    cudaFuncSetAttribute(qkv_kernel, cudaFuncAttributeMaxDynamicSharedMemorySize, SMEM_BYTES);
    cudaFuncSetAttribute(fc2_kernel, cudaFuncAttributeMaxDynamicSharedMemorySize, SMEM_BYTES);

    qkv_kernel<<<dim3(16, QKV_KSPLIT, 3), 256, SMEM_BYTES>>>(x, Wq, Wk, Wv);
    combine_kernel<<<BS / 256, 256>>>();
    attn_kernel<<<dim3(BATCH, 8), 256>>>();
    act_kernel<<<BS / 256, 256>>>(p2);
    fc2_kernel<<<dim3(16, FC2_KSPLIT), 256, SMEM_BYTES>>>(Wfc2);
    ln_kernel<<<BATCH, 512>>>(bfc2, g2, b2, out);
}

// round 11
// speedup vs baseline: 4.3955x; 1.4730x over previous
#include <cuda_runtime.h>
#include <math.h>
#include <stdint.h>

#define BATCH 32
#define S 2048
#define BS (BATCH * S)
#define EPSLN 1e-5f
#define L2E 1.4426950408889634f   // log2(e)

#define QKV_KSPLIT 8
#define FC2_KSPLIT 16
#define NCHEB 64

// ---------------- scratch (no allocations allowed) ----------------
__device__ float g_qp[QKV_KSPLIT * BS];
__device__ float g_kp[QKV_KSPLIT * BS];
__device__ float g_vp[QKV_KSPLIT * BS];
__device__ float g_qc[BS];
__device__ float g_kc[BS];
__device__ float g_vc[BS];
__device__ float g_num[BS];
__device__ float g_act[BS];
__device__ float g_fcp[FC2_KSPLIT * BS];
__device__ float g_Zp[BATCH * 8];
__device__ float g_F[BATCH * NCHEB];
__device__ float g_G[BATCH * NCHEB];
__device__ float g_rqmn[256], g_rqmx[256], g_rkmn[256], g_rkmx[256];

__device__ __forceinline__ float ex2f(float x) {
    float y;
    asm("ex2.approx.f32 %0, %1;" : "=f"(y) : "f"(x));
    return y;
}

__device__ __forceinline__ float cvt_tf32(float x) {
    uint32_t u;
    asm("cvt.rna.tf32.f32 %0, %1;" : "=r"(u) : "f"(x));
    return __uint_as_float(u);
}

__device__ __forceinline__ void mma_tf32(float acc[4],
                                         uint32_t a0, uint32_t a1, uint32_t a2, uint32_t a3,
                                         uint32_t b0, uint32_t b1) {
    asm volatile("mma.sync.aligned.m16n8k8.row.col.f32.tf32.tf32.f32 "
                 "{%0,%1,%2,%3}, {%4,%5,%6,%7}, {%8,%9}, {%0,%1,%2,%3};"
                 : "+f"(acc[0]), "+f"(acc[1]), "+f"(acc[2]), "+f"(acc[3])
                 : "r"(a0), "r"(a1), "r"(a2), "r"(a3), "r"(b0), "r"(b1));
}

__device__ __forceinline__ float f4c(float4 v, int k) {
    return (k == 0) ? v.x : ((k == 1) ? v.y : ((k == 2) ? v.z : v.w));
}

// SMEM geometry for GEMM: fragment-permuted k layout pos(k) = (k%8)*4 + k/8,
// row stride 48 floats -> conflict-free frag LDS.128.
#define PSTRIDE 48
#define SM_A_HI 0
#define SM_A_LO (32 * PSTRIDE)
#define SM_B_HI (64 * PSTRIDE)
#define SM_B_LO (192 * PSTRIDE)
#define SMEM_FLOATS (320 * PSTRIDE)
#define SMEM_BYTES (SMEM_FLOATS * 4)

// ---------------- tensor-core GEMM (3xTF32), unchanged from R9 ----------------
template <int NCHUNK>
__device__ __forceinline__ void gemm_mma(const float* __restrict__ X,
                                         const float* __restrict__ W,
                                         float* __restrict__ out,
                                         int c0, int kb0)
{
    extern __shared__ float sm[];
    float* sAhi = sm + SM_A_HI;
    float* sAlo = sm + SM_A_LO;
    float* sBhi = sm + SM_B_HI;
    float* sBlo = sm + SM_B_LO;

    const int tid = threadIdx.x;
    const int L = tid & 31, w = tid >> 5;
    const int mh = w & 1, ng = w >> 1;

    float acc[4][4];
    #pragma unroll
    for (int i = 0; i < 4; i++)
        #pragma unroll
        for (int j = 0; j < 4; j++) acc[i][j] = 0.f;

    const int posL = ((L & 7) << 2) + (L >> 3);

    float wreg[16], xreg[4];
    #pragma unroll
    for (int i = 0; i < 16; i++)
        wreg[i] = W[(size_t)(c0 + w + 8 * i) * S + kb0 + L];
    #pragma unroll
    for (int i = 0; i < 4; i++)
        xreg[i] = X[(size_t)(w + 8 * i) * S + kb0 + L];

    for (int ch = 0; ch < NCHUNK; ch++) {
        __syncthreads();
        #pragma unroll
        for (int i = 0; i < 16; i++) {
            float v = wreg[i];
            float hi = cvt_tf32(v);
            float lo = cvt_tf32(v - hi);
            sBhi[(w + 8 * i) * PSTRIDE + posL] = hi;
            sBlo[(w + 8 * i) * PSTRIDE + posL] = lo;
        }
        #pragma unroll
        for (int i = 0; i < 4; i++) {
            float v = xreg[i];
            float hi = cvt_tf32(v);
            float lo = cvt_tf32(v - hi);
            sAhi[(w + 8 * i) * PSTRIDE + posL] = hi;
            sAlo[(w + 8 * i) * PSTRIDE + posL] = lo;
        }
        __syncthreads();

        if (ch + 1 < NCHUNK) {
            const int k0 = kb0 + (ch + 1) * 32;
            #pragma unroll
            for (int i = 0; i < 16; i++)
                wreg[i] = W[(size_t)(c0 + w + 8 * i) * S + k0 + L];
            #pragma unroll
            for (int i = 0; i < 4; i++)
                xreg[i] = X[(size_t)(w + 8 * i) * S + k0 + L];
        }

        const int rA = mh * 16 + (L >> 2);
        const int ca = L & 3;
        float4 Ah0 = *(const float4*)&sAhi[rA * PSTRIDE + ca * 4];
        float4 Ah1 = *(const float4*)&sAhi[(rA + 8) * PSTRIDE + ca * 4];
        float4 Ah2 = *(const float4*)&sAhi[rA * PSTRIDE + (ca + 4) * 4];
        float4 Ah3 = *(const float4*)&sAhi[(rA + 8) * PSTRIDE + (ca + 4) * 4];
        float4 Al0 = *(const float4*)&sAlo[rA * PSTRIDE + ca * 4];
        float4 Al1 = *(const float4*)&sAlo[(rA + 8) * PSTRIDE + ca * 4];
        float4 Al2 = *(const float4*)&sAlo[rA * PSTRIDE + (ca + 4) * 4];
        float4 Al3 = *(const float4*)&sAlo[(rA + 8) * PSTRIDE + (ca + 4) * 4];

        #pragma unroll
        for (int nt = 0; nt < 4; nt++) {
            const int nc = (ng * 32 + nt * 8 + (L >> 2)) * PSTRIDE;
            float4 Bh0 = *(const float4*)&sBhi[nc + ca * 4];
            float4 Bh1 = *(const float4*)&sBhi[nc + (ca + 4) * 4];
            float4 Bl0 = *(const float4*)&sBlo[nc + ca * 4];
            float4 Bl1 = *(const float4*)&sBlo[nc + (ca + 4) * 4];
            #pragma unroll
            for (int s = 0; s < 4; s++) {
                uint32_t a0h = __float_as_uint(f4c(Ah0, s));
                uint32_t a1h = __float_as_uint(f4c(Ah1, s));
                uint32_t a2h = __float_as_uint(f4c(Ah2, s));
                uint32_t a3h = __float_as_uint(f4c(Ah3, s));
                uint32_t b0h = __float_as_uint(f4c(Bh0, s));
                uint32_t b1h = __float_as_uint(f4c(Bh1, s));
                mma_tf32(acc[nt], a0h, a1h, a2h, a3h, b0h, b1h);
                mma_tf32(acc[nt], a0h, a1h, a2h, a3h,
                         __float_as_uint(f4c(Bl0, s)), __float_as_uint(f4c(Bl1, s)));
                mma_tf32(acc[nt],
                         __float_as_uint(f4c(Al0, s)), __float_as_uint(f4c(Al1, s)),
                         __float_as_uint(f4c(Al2, s)), __float_as_uint(f4c(Al3, s)),
                         b0h, b1h);
            }
        }
    }

    const int rowO = mh * 16 + (L >> 2);
    #pragma unroll
    for (int nt = 0; nt < 4; nt++) {
        const int colO = c0 + ng * 32 + nt * 8 + 2 * (L & 3);
        *(float2*)&out[(size_t)rowO * S + colO] = make_float2(acc[nt][0], acc[nt][1]);
        *(float2*)&out[(size_t)(rowO + 8) * S + colO] = make_float2(acc[nt][2], acc[nt][3]);
    }
}

// ---------------- kernel 1: fused QKV GEMM ----------------
__global__ void __launch_bounds__(256, 2) qkv_kernel(const float* __restrict__ x,
                                                     const float* __restrict__ Wq,
                                                     const float* __restrict__ Wk,
                                                     const float* __restrict__ Wv) {
    const int z = blockIdx.z;
    const float* W = (z == 0) ? Wq : (z == 1 ? Wk : Wv);
    float* out = ((z == 0) ? g_qp : (z == 1 ? g_kp : g_vp)) + (size_t)blockIdx.y * BS;
    gemm_mma<64 / QKV_KSPLIT>(x, W, out, blockIdx.x * 128,
                              blockIdx.y * (S / QKV_KSPLIT));
}

// ---------------- kernel 1b: combine qkv partials + per-256-chunk min/max ----------------
__global__ void combine_kernel() {
    __shared__ float r0[8], r1[8], r2[8], r3[8];
    const int tid = threadIdx.x;
    const int idx = blockIdx.x * 256 + tid;
    float q = 0.f, k = 0.f, v = 0.f;
    #pragma unroll
    for (int p = 0; p < QKV_KSPLIT; p++) {
        q += g_qp[(size_t)p * BS + idx];
        k += g_kp[(size_t)p * BS + idx];
        v += g_vp[(size_t)p * BS + idx];
    }
    g_qc[idx] = q; g_kc[idx] = k; g_vc[idx] = v;

    float qmn = q, qmx = q, kmn = k, kmx = k;
    #pragma unroll
    for (int off = 16; off > 0; off >>= 1) {
        qmn = fminf(qmn, __shfl_xor_sync(0xffffffffu, qmn, off));
        qmx = fmaxf(qmx, __shfl_xor_sync(0xffffffffu, qmx, off));
        kmn = fminf(kmn, __shfl_xor_sync(0xffffffffu, kmn, off));
        kmx = fmaxf(kmx, __shfl_xor_sync(0xffffffffu, kmx, off));
    }
    const int lane = tid & 31, wid = tid >> 5;
    if (lane == 0) { r0[wid] = qmn; r1[wid] = qmx; r2[wid] = kmn; r3[wid] = kmx; }
    __syncthreads();
    if (tid == 0) {
        float a = r0[0], b = r1[0], c = r2[0], d = r3[0];
        #pragma unroll
        for (int w = 1; w < 8; w++) {
            a = fminf(a, r0[w]); b = fmaxf(b, r1[w]);
            c = fminf(c, r2[w]); d = fmaxf(d, r3[w]);
        }
        g_rqmn[blockIdx.x] = a; g_rqmx[blockIdx.x] = b;
        g_rkmn[blockIdx.x] = c; g_rkmx[blockIdx.x] = d;
    }
}

// batch-level range + shift M (identical fp sequence in both cheb kernels)
__device__ __forceinline__ void batch_range(int b, float& c, float& h, float& M) {
    float qmn = 3.0e38f, qmx = -3.0e38f, kmn = 3.0e38f, kmx = -3.0e38f;
    #pragma unroll
    for (int j = 0; j < 8; j++) {
        qmn = fminf(qmn, g_rqmn[b * 8 + j]);
        qmx = fmaxf(qmx, g_rqmx[b * 8 + j]);
        kmn = fminf(kmn, g_rkmn[b * 8 + j]);
        kmx = fmaxf(kmx, g_rkmx[b * 8 + j]);
    }
    c = 0.5f * (qmn + qmx);
    h = fmaxf(0.5f * (qmx - qmn), 1e-30f);
    M = fmaxf(fmaxf(qmn * kmn, qmn * kmx), fmaxf(qmx * kmn, qmx * kmx));
}

// ---------------- kernel 2a: Chebyshev node evaluation ----------------
// F(t_n) = sum_j v_j e^{t_n k_j - M}, G(t_n) = sum_j e^{t_n k_j - M}
// grid (BATCH, 4): 16 nodes per block (2 per warp), full j range.
__global__ void __launch_bounds__(256) cheb_nodes_kernel() {
    __shared__ float sk[S], sv[S];
    __shared__ float sprm[3];

    const int b = blockIdx.x;
    const int tid = threadIdx.x;
    const int lane = tid & 31, w = tid >> 5;

    for (int idx = tid; idx < S; idx += 256) {
        sk[idx] = g_kc[b * S + idx];
        sv[idx] = g_vc[b * S + idx];
    }
    if (tid == 0) {
        float c, h, M;
        batch_range(b, c, h, M);
        sprm[0] = c; sprm[1] = h; sprm[2] = M;
    }
    __syncthreads();
    const float c = sprm[0], h = sprm[1], Ml2e = sprm[2] * L2E;

    #pragma unroll
    for (int nn = 0; nn < 2; nn++) {
        const int n = blockIdx.y * 16 + w * 2 + nn;
        const float t = fmaf(h, cospif((n + 0.5f) * (1.0f / NCHEB)), c);
        const float tl = t * L2E;
        float F = 0.f, G = 0.f;
        #pragma unroll 4
        for (int j = lane; j < S; j += 32) {
            float e = ex2f(fmaf(tl, sk[j], -Ml2e));
            F = fmaf(e, sv[j], F);
            G += e;
        }
        #pragma unroll
        for (int off = 16; off > 0; off >>= 1) {
            F += __shfl_xor_sync(0xffffffffu, F, off);
            G += __shfl_xor_sync(0xffffffffu, G, off);
        }
        if (lane == 0) {
            g_F[b * NCHEB + n] = F;
            g_G[b * NCHEB + n] = G;
        }
    }
}

// ---------------- kernel 2b: Chebyshev coefficients + Clenshaw eval ----------------
// grid (BATCH, 4): each block evaluates 512 i's; writes num_i = F(q_i), Z partial = sum G(q_i).
__global__ void __launch_bounds__(256) cheb_eval_kernel() {
    __shared__ float scos[NCHEB][NCHEB + 1];
    __shared__ float sF[NCHEB], sG[NCHEB], saF[NCHEB], saG[NCHEB];
    __shared__ float sprm[2];
    __shared__ float rz[8];

    const int b = blockIdx.x;
    const int tid = threadIdx.x;
    const int lane = tid & 31, wid = tid >> 5;

    if (tid == 0) {
        float c, h, M;
        batch_range(b, c, h, M);
        sprm[0] = c; sprm[1] = h;
    }
    if (tid < NCHEB) {
        sF[tid] = g_F[b * NCHEB + tid];
        sG[tid] = g_G[b * NCHEB + tid];
    }
    // cos table: scos[m][n] = cos(pi * m * (2n+1) / 128)  (exact rational args)
    for (int idx = tid; idx < NCHEB * NCHEB; idx += 256) {
        int m = idx >> 6, n = idx & 63;
        scos[m][n] = cospif((float)(m * (2 * n + 1)) * (1.0f / (2 * NCHEB)));
    }
    __syncthreads();

    // coefficients: a_m = scale * sum_n src[n] * cos(m theta_n)
    if (tid < 2 * NCHEB) {
        const int m = tid & 63;
        const float* src = (tid < NCHEB) ? sF : sG;
        float s = 0.f;
        #pragma unroll 8
        for (int n = 0; n < NCHEB; n++)
            s = fmaf(src[n], scos[m][n], s);
        s *= (m == 0) ? (1.0f / NCHEB) : (2.0f / NCHEB);
        if (tid < NCHEB) saF[m] = s; else saG[m] = s;
    }
    __syncthreads();

    const float c = sprm[0], hinv = 1.0f / sprm[1];

    // Clenshaw for 2 i's per thread, F and G together
    const int i0 = blockIdx.y * 512 + tid;
    float ta = g_qc[b * S + i0];
    float tb = g_qc[b * S + i0 + 256];
    float ua = fminf(1.f, fmaxf(-1.f, (ta - c) * hinv));
    float ub = fminf(1.f, fmaxf(-1.f, (tb - c) * hinv));
    float ua2 = ua + ua, ub2 = ub + ub;

    float fa1 = 0.f, fa2 = 0.f, ga1 = 0.f, ga2 = 0.f;
    float fb1 = 0.f, fb2 = 0.f, gb1 = 0.f, gb2 = 0.f;
    #pragma unroll
    for (int m = NCHEB - 1; m >= 1; m--) {
        const float af = saF[m], ag = saG[m];
        float nfa = fmaf(ua2, fa1, af - fa2); fa2 = fa1; fa1 = nfa;
        float nga = fmaf(ua2, ga1, ag - ga2); ga2 = ga1; ga1 = nga;
        float nfb = fmaf(ub2, fb1, af - fb2); fb2 = fb1; fb1 = nfb;
        float ngb = fmaf(ub2, gb1, ag - gb2); gb2 = gb1; gb1 = ngb;
    }
    const float a0f = saF[0], a0g = saG[0];
    float Fa = fmaf(ua, fa1, a0f - fa2);
    float Ga = fmaf(ua, ga1, a0g - ga2);
    float Fb = fmaf(ub, fb1, a0f - fb2);
    float Gb = fmaf(ub, gb1, a0g - gb2);

    g_num[b * S + i0] = Fa;
    g_num[b * S + i0 + 256] = Fb;

    float z = Ga + Gb;
    #pragma unroll
    for (int off = 16; off > 0; off >>= 1)
        z += __shfl_xor_sync(0xffffffffu, z, off);
    if (lane == 0) rz[wid] = z;
    __syncthreads();
    if (tid == 0) {
        float tot = rz[0];
        #pragma unroll
        for (int w = 1; w < 8; w++) tot += rz[w];
        g_Zp[b * 8 + blockIdx.y] = tot;
    }
}

// ---------------- kernel 3: divide by Z + OptimActivation ----------------
__global__ void act_kernel(const float* __restrict__ p2) {
    const int idx = blockIdx.x * 256 + threadIdx.x;
    const int b = idx >> 11;

    float Z = 0.f;
    #pragma unroll
    for (int pz = 0; pz < 4; pz++) Z += g_Zp[b * 8 + pz];

    float p[5];
    #pragma unroll
    for (int t = 0; t < 5; t++) p[t] = p2[t];
    float pm = p[0];
    #pragma unroll
    for (int t = 1; t < 5; t++) pm = fmaxf(pm, p[t]);
    float pe[5], psum = 0.f;
    #pragma unroll
    for (int t = 0; t < 5; t++) { pe[t] = ex2f((p[t] - pm) * L2E); psum += pe[t]; }
    const float inv = __fdividef(1.0f, psum);
    const float ps0 = pe[0] * inv, ps1 = pe[1] * inv, ps2 = pe[2] * inv;

    const float val = __fdividef(g_num[idx], Z);
    const float sig = __fdividef(1.0f, 1.0f + ex2f(-val * L2E));
    g_act[idx] = sig * val * ps0 + __sinf(val) * ps1 + val * ps2;
}

// ---------------- kernel 4: fc2 GEMM, grid (16 ctiles, 16 ksplit) ----------------
__global__ void __launch_bounds__(256, 2) fc2_kernel(const float* __restrict__ W) {
    gemm_mma<64 / FC2_KSPLIT>(g_act, W, g_fcp + (size_t)blockIdx.y * BS,
                              blockIdx.x * 128, blockIdx.y * (S / FC2_KSPLIT));
}

// ---------------- kernel 5: combine fc2 partials + bias + LayerNorm ----------------
__global__ void ln_kernel(const float* __restrict__ bias,
                          const float* __restrict__ g2,
                          const float* __restrict__ b2,
                          float* __restrict__ out) {
    __shared__ float sRow[S];
    __shared__ float rsum[16], rsq[16];
    __shared__ float sMu, sRstd;

    const int b = blockIdx.x;
    const int tid = threadIdx.x;
    const int lane = tid & 31, wid = tid >> 5;

    float s = 0.f, s2 = 0.f;
    #pragma unroll
    for (int it = 0; it < 4; it++) {
        int idx = tid + it * 512;
        float v = bias[idx];
        #pragma unroll
        for (int p = 0; p < FC2_KSPLIT; p++)
            v += g_fcp[(size_t)p * BS + b * S + idx];
        sRow[idx] = v;
        s += v;
        s2 = fmaf(v, v, s2);
    }
    #pragma unroll
    for (int off = 16; off > 0; off >>= 1) {
        s  += __shfl_xor_sync(0xffffffffu, s,  off);
        s2 += __shfl_xor_sync(0xffffffffu, s2, off);
    }
    if (lane == 0) { rsum[wid] = s; rsq[wid] = s2; }
    __syncthreads();
    if (tid == 0) {
        float ts = 0.f, ts2 = 0.f;
        #pragma unroll
        for (int w = 0; w < 16; w++) { ts += rsum[w]; ts2 += rsq[w]; }
        float mu = ts * (1.0f / S);
        float var = ts2 * (1.0f / S) - mu * mu;
        sMu = mu;
        sRstd = rsqrtf(var + EPSLN);
    }
    __syncthreads();

    const float mu = sMu, rstd = sRstd;
    #pragma unroll
    for (int it = 0; it < 4; it++) {
        int idx = tid + it * 512;
        out[b * S + idx] = (sRow[idx] - mu) * rstd * g2[idx] + b2[idx];
    }
}

// ---------------- launch ----------------
extern "C" void kernel_launch(void* const* d_in, const int* in_sizes, int n_in,
                              void* d_out, int out_size) {
    const float* x    = (const float*)d_in[0];
    const float* Wq   = (const float*)d_in[1];
    const float* Wk   = (const float*)d_in[2];
    const float* Wv   = (const float*)d_in[3];
    const float* p2   = (const float*)d_in[4];
    const float* Wfc2 = (const float*)d_in[5];
    const float* bfc2 = (const float*)d_in[6];
    const float* g2   = (const float*)d_in[7];
    const float* b2   = (const float*)d_in[8];
    float* out = (float*)d_out;

    cudaFuncSetAttribute(qkv_kernel, cudaFuncAttributeMaxDynamicSharedMemorySize, SMEM_BYTES);
    cudaFuncSetAttribute(fc2_kernel, cudaFuncAttributeMaxDynamicSharedMemorySize, SMEM_BYTES);

    qkv_kernel<<<dim3(16, QKV_KSPLIT, 3), 256, SMEM_BYTES>>>(x, Wq, Wk, Wv);
    combine_kernel<<<BS / 256, 256>>>();
    cheb_nodes_kernel<<<dim3(BATCH, 4), 256>>>();
    cheb_eval_kernel<<<dim3(BATCH, 4), 256>>>();
    act_kernel<<<BS / 256, 256>>>(p2);
    fc2_kernel<<<dim3(16, FC2_KSPLIT), 256, SMEM_BYTES>>>(Wfc2);
    ln_kernel<<<BATCH, 512>>>(bfc2, g2, b2, out);
}

// round 12
// speedup vs baseline: 7.1356x; 1.6234x over previous
#include <cuda_runtime.h>
#include <math.h>
#include <stdint.h>

#define BATCH 32
#define S 2048
#define BS (BATCH * S)
#define EPSLN 1e-5f
#define L2E 1.4426950408889634f   // log2(e)

#define QKV_KSPLIT 8
#define FC2_KSPLIT 16
#define NCHEB 40

// ---------------- scratch (no allocations allowed) ----------------
__device__ float g_qp[QKV_KSPLIT * BS];
__device__ float g_kp[QKV_KSPLIT * BS];
__device__ float g_vp[QKV_KSPLIT * BS];
__device__ float g_qc[BS];
__device__ float g_kc[BS];
__device__ float g_vc[BS];
__device__ float g_act[BS];
__device__ float g_fcp[FC2_KSPLIT * BS];
__device__ float g_F[BATCH * NCHEB];
__device__ float g_G[BATCH * NCHEB];
__device__ float g_rqmn[256], g_rqmx[256], g_rkmn[256], g_rkmx[256];

__device__ __forceinline__ float ex2f(float x) {
    float y;
    asm("ex2.approx.f32 %0, %1;" : "=f"(y) : "f"(x));
    return y;
}

__device__ __forceinline__ void cp_async16(unsigned dst, const void* src) {
    asm volatile("cp.async.cg.shared.global [%0], [%1], 16;" :: "r"(dst), "l"(src));
}

// split float2 (x = even-k, y = odd-k) into packed bf16x2 hi and lo planes.
// hi rounded (cvt.rn) -> lo unbiased; dropped lo*lo term ~2^-18 relative.
__device__ __forceinline__ void bsplit(float2 v, uint32_t& hi, uint32_t& lo) {
    uint32_t h;
    asm("cvt.rn.bf16x2.f32 %0, %1, %2;" : "=r"(h) : "f"(v.y), "f"(v.x));
    float fx = __uint_as_float(h << 16);
    float fy = __uint_as_float(h & 0xffff0000u);
    float lx = v.x - fx, ly = v.y - fy;
    uint32_t l;
    asm("cvt.rn.bf16x2.f32 %0, %1, %2;" : "=r"(l) : "f"(ly), "f"(lx));
    hi = h; lo = l;
}

__device__ __forceinline__ void mma_bf16(float acc[4],
                                         uint32_t a0, uint32_t a1, uint32_t a2, uint32_t a3,
                                         uint32_t b0, uint32_t b1) {
    asm volatile("mma.sync.aligned.m16n8k16.row.col.f32.bf16.bf16.f32 "
                 "{%0,%1,%2,%3}, {%4,%5,%6,%7}, {%8,%9}, {%0,%1,%2,%3};"
                 : "+f"(acc[0]), "+f"(acc[1]), "+f"(acc[2]), "+f"(acc[3])
                 : "r"(a0), "r"(a1), "r"(a2), "r"(a3), "r"(b0), "r"(b1));
}

// ---------------- bf16 tensor-core GEMM: out[b, c] = X[b,:] . W[c,:] ----------------
// MMA M-axis = W cols (c), N-axis = batch. Block: 256 thr / 8 warps, tile 128c x 32b,
// K-chunk 32 (2 k16-steps). W raw fp32 in smem via cp.async (double buffer, row stride
// 40 floats -> conflict-free LDS.64 frags), split to bf16 hi/lo at consume (once per elem).
// X staged per chunk pre-split into B-fragment slot order: 1 LDS.64 per (k16, n8) frag.
#define WSTRIDE 40
#define WSTAGE (128 * WSTRIDE)

template <int NCHUNK>
__device__ __forceinline__ void gemm_bf16(const float* __restrict__ X,
                                          const float* __restrict__ W,
                                          float* __restrict__ out,
                                          int c0, int kb0)
{
    __shared__ __align__(16) float sW[2][WSTAGE];
    __shared__ uint32_t sXh[512], sXl[512];

    const int tid = threadIdx.x;
    const int lane = tid & 31, w = tid >> 5;

    float acc[4][4];
    #pragma unroll
    for (int g = 0; g < 4; g++)
        #pragma unroll
        for (int j = 0; j < 4; j++) acc[g][j] = 0.f;

    const unsigned swbase = (unsigned)__cvta_generic_to_shared(&sW[0][0]);

    // W loader: idx = tid + i*256 -> row = idx>>3 (0..127), quad = idx&7
    const int wrow = tid >> 3, wq = tid & 7;

    // X slot decode: this thread owns slots (s=0, rem=tid) and (s=1, rem=tid)
    const int sg   = tid >> 6;              // n8 group
    const int sln  = (tid >> 1) & 31;       // consuming lane
    const int sbrg = tid & 1;               // b-reg (0: k 0..1, 1: k 8..9)
    const int sn   = sg * 8 + (sln >> 2);
    const int skk  = sbrg * 8 + 2 * (sln & 3);
    const float* xp = X + (size_t)sn * S + kb0 + skk;

    // ---- prologue: W chunk 0 -> stage 0, X chunk 0 -> regs ----
    #pragma unroll
    for (int i = 0; i < 4; i++) {
        int r = wrow + i * 32;
        cp_async16(swbase + (unsigned)((r * WSTRIDE + wq * 4) * 4),
                   W + (size_t)(c0 + r) * S + kb0 + wq * 4);
    }
    asm volatile("cp.async.commit_group;");
    float2 xr0 = *(const float2*)(xp);
    float2 xr1 = *(const float2*)(xp + 16);

    for (int ch = 0; ch < NCHUNK; ch++) {
        asm volatile("cp.async.wait_group 0;");
        __syncthreads();   // all prev compute done; W stage ch visible

        if (ch + 1 < NCHUNK) {
            const int kb = kb0 + (ch + 1) * 32;
            const unsigned stoff = (unsigned)(((ch + 1) & 1) * WSTAGE * 4);
            #pragma unroll
            for (int i = 0; i < 4; i++) {
                int r = wrow + i * 32;
                cp_async16(swbase + stoff + (unsigned)((r * WSTRIDE + wq * 4) * 4),
                           W + (size_t)(c0 + r) * S + kb + wq * 4);
            }
            asm volatile("cp.async.commit_group;");
        }

        // stage X slots (pre-split, fragment order)
        {
            uint32_t h0, l0, h1, l1;
            bsplit(xr0, h0, l0);
            bsplit(xr1, h1, l1);
            sXh[tid] = h0;       sXl[tid] = l0;        // s = 0
            sXh[tid + 256] = h1; sXl[tid + 256] = l1;  // s = 1
        }
        if (ch + 1 < NCHUNK) {
            xr0 = *(const float2*)(xp + (ch + 1) * 32);
            xr1 = *(const float2*)(xp + (ch + 1) * 32 + 16);
        }
        __syncthreads();

        const float* ws = sW[ch & 1];
        const int rb = w * 16 + (lane >> 2);
        const int kc = 2 * (lane & 3);

        #pragma unroll
        for (int s = 0; s < 2; s++) {
            // A raw frags (4 LDS.64), split to hi/lo
            float2 ra0 = *(const float2*)&ws[rb * WSTRIDE + s * 16 + kc];
            float2 ra2 = *(const float2*)&ws[rb * WSTRIDE + s * 16 + 8 + kc];
            float2 ra1 = *(const float2*)&ws[(rb + 8) * WSTRIDE + s * 16 + kc];
            float2 ra3 = *(const float2*)&ws[(rb + 8) * WSTRIDE + s * 16 + 8 + kc];
            uint32_t A0h, A0l, A1h, A1l, A2h, A2l, A3h, A3l;
            bsplit(ra0, A0h, A0l);
            bsplit(ra1, A1h, A1l);
            bsplit(ra2, A2h, A2l);
            bsplit(ra3, A3h, A3l);

            #pragma unroll
            for (int g = 0; g < 4; g++) {
                const int base = ((s * 4 + g) << 6) + (lane << 1);
                uint2 bh = *(const uint2*)&sXh[base];
                uint2 bl = *(const uint2*)&sXl[base];
                mma_bf16(acc[g], A0h, A1h, A2h, A3h, bh.x, bh.y);   // hi*hi
                mma_bf16(acc[g], A0h, A1h, A2h, A3h, bl.x, bl.y);   // hi(W)*lo(X)
                mma_bf16(acc[g], A0l, A1l, A2l, A3l, bh.x, bh.y);   // lo(W)*hi(X)
            }
        }
    }

    const int c = c0 + w * 16 + (lane >> 2);
    #pragma unroll
    for (int g = 0; g < 4; g++) {
        const int b = g * 8 + 2 * (lane & 3);
        out[(size_t)b * S + c]           = acc[g][0];
        out[(size_t)(b + 1) * S + c]     = acc[g][1];
        out[(size_t)b * S + c + 8]       = acc[g][2];
        out[(size_t)(b + 1) * S + c + 8] = acc[g][3];
    }
}

// ---------------- kernel 1: fused QKV GEMM, grid (16 ctiles, 8 ksplit, 3) ----------------
__global__ void __launch_bounds__(256) qkv_kernel(const float* __restrict__ x,
                                                  const float* __restrict__ Wq,
                                                  const float* __restrict__ Wk,
                                                  const float* __restrict__ Wv) {
    const int z = blockIdx.z;
    const float* W = (z == 0) ? Wq : (z == 1 ? Wk : Wv);
    float* out = ((z == 0) ? g_qp : (z == 1 ? g_kp : g_vp)) + (size_t)blockIdx.y * BS;
    gemm_bf16<(S / QKV_KSPLIT) / 32>(x, W, out, blockIdx.x * 128,
                                     blockIdx.y * (S / QKV_KSPLIT));
}

// ---------------- kernel 1b: combine qkv partials + per-256-chunk min/max ----------------
__global__ void combine_kernel() {
    __shared__ float r0[8], r1[8], r2[8], r3[8];
    const int tid = threadIdx.x;
    const int idx = blockIdx.x * 256 + tid;
    float q = 0.f, k = 0.f, v = 0.f;
    #pragma unroll
    for (int p = 0; p < QKV_KSPLIT; p++) {
        q += g_qp[(size_t)p * BS + idx];
        k += g_kp[(size_t)p * BS + idx];
        v += g_vp[(size_t)p * BS + idx];
    }
    g_qc[idx] = q; g_kc[idx] = k; g_vc[idx] = v;

    float qmn = q, qmx = q, kmn = k, kmx = k;
    #pragma unroll
    for (int off = 16; off > 0; off >>= 1) {
        qmn = fminf(qmn, __shfl_xor_sync(0xffffffffu, qmn, off));
        qmx = fmaxf(qmx, __shfl_xor_sync(0xffffffffu, qmx, off));
        kmn = fminf(kmn, __shfl_xor_sync(0xffffffffu, kmn, off));
        kmx = fmaxf(kmx, __shfl_xor_sync(0xffffffffu, kmx, off));
    }
    const int lane = tid & 31, wid = tid >> 5;
    if (lane == 0) { r0[wid] = qmn; r1[wid] = qmx; r2[wid] = kmn; r3[wid] = kmx; }
    __syncthreads();
    if (tid == 0) {
        float a = r0[0], b = r1[0], c = r2[0], d = r3[0];
        #pragma unroll
        for (int w = 1; w < 8; w++) {
            a = fminf(a, r0[w]); b = fmaxf(b, r1[w]);
            c = fminf(c, r2[w]); d = fmaxf(d, r3[w]);
        }
        g_rqmn[blockIdx.x] = a; g_rqmx[blockIdx.x] = b;
        g_rkmn[blockIdx.x] = c; g_rkmx[blockIdx.x] = d;
    }
}

// batch-level range + shift M (identical fp sequence wherever used)
__device__ __forceinline__ void batch_range(int b, float& c, float& h, float& M) {
    float qmn = 3.0e38f, qmx = -3.0e38f, kmn = 3.0e38f, kmx = -3.0e38f;
    #pragma unroll
    for (int j = 0; j < 8; j++) {
        qmn = fminf(qmn, g_rqmn[b * 8 + j]);
        qmx = fmaxf(qmx, g_rqmx[b * 8 + j]);
        kmn = fminf(kmn, g_rkmn[b * 8 + j]);
        kmx = fmaxf(kmx, g_rkmx[b * 8 + j]);
    }
    c = 0.5f * (qmn + qmx);
    h = fmaxf(0.5f * (qmx - qmn), 1e-30f);
    M = fmaxf(fmaxf(qmn * kmn, qmn * kmx), fmaxf(qmx * kmn, qmx * kmx));
}

// ---------------- kernel 2a: Chebyshev node evaluation ----------------
// F(t_n) = sum_j v_j e^{t_n k_j - M}, G(t_n) = sum_j e^{t_n k_j - M}
// grid (BATCH, 5): 8 nodes per block (1 per warp).
__global__ void __launch_bounds__(256) cheb_nodes_kernel() {
    __shared__ float sk[S], sv[S];
    __shared__ float sprm[3];

    const int b = blockIdx.x;
    const int tid = threadIdx.x;
    const int lane = tid & 31, w = tid >> 5;

    for (int idx = tid; idx < S; idx += 256) {
        sk[idx] = g_kc[b * S + idx];
        sv[idx] = g_vc[b * S + idx];
    }
    if (tid == 0) {
        float c, h, M;
        batch_range(b, c, h, M);
        sprm[0] = c; sprm[1] = h; sprm[2] = M;
    }
    __syncthreads();
    const float c = sprm[0], h = sprm[1], Ml2e = sprm[2] * L2E;

    const int n = blockIdx.y * 8 + w;
    const float t = fmaf(h, cospif((n + 0.5f) * (1.0f / NCHEB)), c);
    const float tl = t * L2E;
    float F = 0.f, G = 0.f;
    #pragma unroll 4
    for (int j = lane; j < S; j += 32) {
        float e = ex2f(fmaf(tl, sk[j], -Ml2e));
        F = fmaf(e, sv[j], F);
        G += e;
    }
    #pragma unroll
    for (int off = 16; off > 0; off >>= 1) {
        F += __shfl_xor_sync(0xffffffffu, F, off);
        G += __shfl_xor_sync(0xffffffffu, G, off);
    }
    if (lane == 0) {
        g_F[b * NCHEB + n] = F;
        g_G[b * NCHEB + n] = G;
    }
}

// ---------------- kernel 2b: coefficients + Clenshaw eval + Z + activation (fused) ----
// grid (BATCH), block 512; 4 i's per thread. Z reduced in-block -> act applied in-place.
__global__ void __launch_bounds__(512) cheb_evalact_kernel(const float* __restrict__ p2) {
    __shared__ float scos[NCHEB][NCHEB + 1];
    __shared__ float sF[NCHEB], sG[NCHEB], saF[NCHEB], saG[NCHEB];
    __shared__ float sprm[2];
    __shared__ float rz[16];
    __shared__ float sZ, sPs0, sPs1, sPs2;

    const int b = blockIdx.x;
    const int tid = threadIdx.x;
    const int lane = tid & 31, wid = tid >> 5;

    if (tid == 0) {
        float c, h, M;
        batch_range(b, c, h, M);
        sprm[0] = c; sprm[1] = h;
    }
    if (tid == 32) {
        // softmax over 5 activation params
        float p[5];
        #pragma unroll
        for (int t = 0; t < 5; t++) p[t] = p2[t];
        float pm = p[0];
        #pragma unroll
        for (int t = 1; t < 5; t++) pm = fmaxf(pm, p[t]);
        float pe[5], psum = 0.f;
        #pragma unroll
        for (int t = 0; t < 5; t++) { pe[t] = ex2f((p[t] - pm) * L2E); psum += pe[t]; }
        float inv = __fdividef(1.0f, psum);
        sPs0 = pe[0] * inv; sPs1 = pe[1] * inv; sPs2 = pe[2] * inv;
    }
    if (tid < NCHEB) {
        sF[tid] = g_F[b * NCHEB + tid];
        sG[tid] = g_G[b * NCHEB + tid];
    }
    for (int idx = tid; idx < NCHEB * NCHEB; idx += 512) {
        int m = idx / NCHEB, n = idx - m * NCHEB;
        scos[m][n] = cospif((float)(m * (2 * n + 1)) * (1.0f / (2 * NCHEB)));
    }
    __syncthreads();

    if (tid < 2 * NCHEB) {
        const int m = (tid < NCHEB) ? tid : (tid - NCHEB);
        const float* src = (tid < NCHEB) ? sF : sG;
        float s = 0.f;
        #pragma unroll 8
        for (int n = 0; n < NCHEB; n++)
            s = fmaf(src[n], scos[m][n], s);
        s *= (m == 0) ? (1.0f / NCHEB) : (2.0f / NCHEB);
        if (tid < NCHEB) saF[m] = s; else saG[m] = s;
    }
    __syncthreads();

    const float c = sprm[0], hinv = 1.0f / sprm[1];

    float Fv[4], Gv[4];
    float zsum = 0.f;
    #pragma unroll
    for (int jj = 0; jj < 4; jj++) {
        const int i = tid + jj * 512;
        float t = g_qc[b * S + i];
        float u = fminf(1.f, fmaxf(-1.f, (t - c) * hinv));
        float u2 = u + u;
        float f1 = 0.f, f2 = 0.f, g1 = 0.f, g2 = 0.f;
        #pragma unroll
        for (int m = NCHEB - 1; m >= 1; m--) {
            const float af = saF[m], ag = saG[m];
            float nf = fmaf(u2, f1, af - f2); f2 = f1; f1 = nf;
            float ng = fmaf(u2, g1, ag - g2); g2 = g1; g1 = ng;
        }
        Fv[jj] = fmaf(u, f1, saF[0] - f2);
        Gv[jj] = fmaf(u, g1, saG[0] - g2);
        zsum += Gv[jj];
    }

    #pragma unroll
    for (int off = 16; off > 0; off >>= 1)
        zsum += __shfl_xor_sync(0xffffffffu, zsum, off);
    if (lane == 0) rz[wid] = zsum;
    __syncthreads();
    if (tid == 0) {
        float tot = rz[0];
        #pragma unroll
        for (int w = 1; w < 16; w++) tot += rz[w];
        sZ = tot;
    }
    __syncthreads();

    const float Z = sZ;
    const float ps0 = sPs0, ps1 = sPs1, ps2 = sPs2;
    #pragma unroll
    for (int jj = 0; jj < 4; jj++) {
        const int i = tid + jj * 512;
        const float val = __fdividef(Fv[jj], Z);
        const float sig = __fdividef(1.0f, 1.0f + ex2f(-val * L2E));
        g_act[b * S + i] = sig * val * ps0 + __sinf(val) * ps1 + val * ps2;
    }
}

// ---------------- kernel 4: fc2 GEMM, grid (16 ctiles, 16 ksplit) ----------------
__global__ void __launch_bounds__(256) fc2_kernel(const float* __restrict__ W) {
    gemm_bf16<(S / FC2_KSPLIT) / 32>(g_act, W, g_fcp + (size_t)blockIdx.y * BS,
                                     blockIdx.x * 128, blockIdx.y * (S / FC2_KSPLIT));
}

// ---------------- kernel 5: combine fc2 partials + bias + LayerNorm ----------------
__global__ void ln_kernel(const float* __restrict__ bias,
                          const float* __restrict__ g2,
                          const float* __restrict__ b2,
                          float* __restrict__ out) {
    __shared__ float sRow[S];
    __shared__ float rsum[16], rsq[16];
    __shared__ float sMu, sRstd;

    const int b = blockIdx.x;
    const int tid = threadIdx.x;
    const int lane = tid & 31, wid = tid >> 5;

    float s = 0.f, s2 = 0.f;
    #pragma unroll
    for (int it = 0; it < 4; it++) {
        int idx = tid + it * 512;
        float v = bias[idx];
        #pragma unroll
        for (int p = 0; p < FC2_KSPLIT; p++)
            v += g_fcp[(size_t)p * BS + b * S + idx];
        sRow[idx] = v;
        s += v;
        s2 = fmaf(v, v, s2);
    }
    #pragma unroll
    for (int off = 16; off > 0; off >>= 1) {
        s  += __shfl_xor_sync(0xffffffffu, s,  off);
        s2 += __shfl_xor_sync(0xffffffffu, s2, off);
    }
    if (lane == 0) { rsum[wid] = s; rsq[wid] = s2; }
    __syncthreads();
    if (tid == 0) {
        float ts = 0.f, ts2 = 0.f;
        #pragma unroll
        for (int w = 0; w < 16; w++) { ts += rsum[w]; ts2 += rsq[w]; }
        float mu = ts * (1.0f / S);
        float var = ts2 * (1.0f / S) - mu * mu;
        sMu = mu;
        sRstd = rsqrtf(var + EPSLN);
    }
    __syncthreads();

    const float mu = sMu, rstd = sRstd;
    #pragma unroll
    for (int it = 0; it < 4; it++) {
        int idx = tid + it * 512;
        out[b * S + idx] = (sRow[idx] - mu) * rstd * g2[idx] + b2[idx];
    }
}

// ---------------- launch ----------------
extern "C" void kernel_launch(void* const* d_in, const int* in_sizes, int n_in,
                              void* d_out, int out_size) {
    const float* x    = (const float*)d_in[0];
    const float* Wq   = (const float*)d_in[1];
    const float* Wk   = (const float*)d_in[2];
    const float* Wv   = (const float*)d_in[3];
    const float* p2   = (const float*)d_in[4];
    const float* Wfc2 = (const float*)d_in[5];
    const float* bfc2 = (const float*)d_in[6];
    const float* g2   = (const float*)d_in[7];
    const float* b2   = (const float*)d_in[8];
    float* out = (float*)d_out;

    qkv_kernel<<<dim3(16, QKV_KSPLIT, 3), 256>>>(x, Wq, Wk, Wv);
    combine_kernel<<<BS / 256, 256>>>();
    cheb_nodes_kernel<<<dim3(BATCH, 5), 256>>>();
    cheb_evalact_kernel<<<BATCH, 512>>>(p2);
    fc2_kernel<<<dim3(16, FC2_KSPLIT), 256>>>(Wfc2);
    ln_kernel<<<BATCH, 512>>>(bfc2, g2, b2, out);
}

// round 13
// speedup vs baseline: 7.5330x; 1.0557x over previous
#include <cuda_runtime.h>
#include <math.h>
#include <stdint.h>

#define BATCH 32
#define S 2048
#define BS (BATCH * S)
#define EPSLN 1e-5f
#define L2E 1.4426950408889634f   // log2(e)

#define QKV_KSPLIT 8
#define FC2_KSPLIT 16
#define NCHEB 40

// ---------------- scratch (no allocations allowed) ----------------
__device__ float g_qp[QKV_KSPLIT * BS];
__device__ float g_kp[QKV_KSPLIT * BS];
__device__ float g_vp[QKV_KSPLIT * BS];
__device__ float g_qc[BS];
__device__ float g_kc[BS];
__device__ float g_vc[BS];
__device__ float g_act[BS];
__device__ float g_fcp[FC2_KSPLIT * BS];
__device__ float g_F[BATCH * NCHEB];
__device__ float g_G[BATCH * NCHEB];
__device__ float g_S[BATCH * NCHEB];   // Chebyshev moments of q: S_m = sum_i T_m(u_i)
__device__ float g_rqmn[256], g_rqmx[256], g_rkmn[256], g_rkmx[256];

__device__ __forceinline__ float ex2f(float x) {
    float y;
    asm("ex2.approx.f32 %0, %1;" : "=f"(y) : "f"(x));
    return y;
}

__device__ __forceinline__ void cp_async16(unsigned dst, const void* src) {
    asm volatile("cp.async.cg.shared.global [%0], [%1], 16;" :: "r"(dst), "l"(src));
}

// split float2 (x = even-k, y = odd-k) into packed bf16x2 hi and lo planes.
__device__ __forceinline__ void bsplit(float2 v, uint32_t& hi, uint32_t& lo) {
    uint32_t h;
    asm("cvt.rn.bf16x2.f32 %0, %1, %2;" : "=r"(h) : "f"(v.y), "f"(v.x));
    float fx = __uint_as_float(h << 16);
    float fy = __uint_as_float(h & 0xffff0000u);
    float lx = v.x - fx, ly = v.y - fy;
    uint32_t l;
    asm("cvt.rn.bf16x2.f32 %0, %1, %2;" : "=r"(l) : "f"(ly), "f"(lx));
    hi = h; lo = l;
}

__device__ __forceinline__ void mma_bf16(float acc[4],
                                         uint32_t a0, uint32_t a1, uint32_t a2, uint32_t a3,
                                         uint32_t b0, uint32_t b1) {
    asm volatile("mma.sync.aligned.m16n8k16.row.col.f32.bf16.bf16.f32 "
                 "{%0,%1,%2,%3}, {%4,%5,%6,%7}, {%8,%9}, {%0,%1,%2,%3};"
                 : "+f"(acc[0]), "+f"(acc[1]), "+f"(acc[2]), "+f"(acc[3])
                 : "r"(a0), "r"(a1), "r"(a2), "r"(a3), "r"(b0), "r"(b1));
}

// ---------------- bf16 tensor-core GEMM (unchanged from R12) ----------------
#define WSTRIDE 40
#define WSTAGE (128 * WSTRIDE)

template <int NCHUNK>
__device__ __forceinline__ void gemm_bf16(const float* __restrict__ X,
                                          const float* __restrict__ W,
                                          float* __restrict__ out,
                                          int c0, int kb0)
{
    __shared__ __align__(16) float sW[2][WSTAGE];
    __shared__ uint32_t sXh[512], sXl[512];

    const int tid = threadIdx.x;
    const int lane = tid & 31, w = tid >> 5;

    float acc[4][4];
    #pragma unroll
    for (int g = 0; g < 4; g++)
        #pragma unroll
        for (int j = 0; j < 4; j++) acc[g][j] = 0.f;

    const unsigned swbase = (unsigned)__cvta_generic_to_shared(&sW[0][0]);

    const int wrow = tid >> 3, wq = tid & 7;

    const int sg   = tid >> 6;
    const int sln  = (tid >> 1) & 31;
    const int sbrg = tid & 1;
    const int sn   = sg * 8 + (sln >> 2);
    const int skk  = sbrg * 8 + 2 * (sln & 3);
    const float* xp = X + (size_t)sn * S + kb0 + skk;

    #pragma unroll
    for (int i = 0; i < 4; i++) {
        int r = wrow + i * 32;
        cp_async16(swbase + (unsigned)((r * WSTRIDE + wq * 4) * 4),
                   W + (size_t)(c0 + r) * S + kb0 + wq * 4);
    }
    asm volatile("cp.async.commit_group;");
    float2 xr0 = *(const float2*)(xp);
    float2 xr1 = *(const float2*)(xp + 16);

    for (int ch = 0; ch < NCHUNK; ch++) {
        asm volatile("cp.async.wait_group 0;");
        __syncthreads();

        if (ch + 1 < NCHUNK) {
            const int kb = kb0 + (ch + 1) * 32;
            const unsigned stoff = (unsigned)(((ch + 1) & 1) * WSTAGE * 4);
            #pragma unroll
            for (int i = 0; i < 4; i++) {
                int r = wrow + i * 32;
                cp_async16(swbase + stoff + (unsigned)((r * WSTRIDE + wq * 4) * 4),
                           W + (size_t)(c0 + r) * S + kb + wq * 4);
            }
            asm volatile("cp.async.commit_group;");
        }

        {
            uint32_t h0, l0, h1, l1;
            bsplit(xr0, h0, l0);
            bsplit(xr1, h1, l1);
            sXh[tid] = h0;       sXl[tid] = l0;
            sXh[tid + 256] = h1; sXl[tid + 256] = l1;
        }
        if (ch + 1 < NCHUNK) {
            xr0 = *(const float2*)(xp + (ch + 1) * 32);
            xr1 = *(const float2*)(xp + (ch + 1) * 32 + 16);
        }
        __syncthreads();

        const float* ws = sW[ch & 1];
        const int rb = w * 16 + (lane >> 2);
        const int kc = 2 * (lane & 3);

        #pragma unroll
        for (int s = 0; s < 2; s++) {
            float2 ra0 = *(const float2*)&ws[rb * WSTRIDE + s * 16 + kc];
            float2 ra2 = *(const float2*)&ws[rb * WSTRIDE + s * 16 + 8 + kc];
            float2 ra1 = *(const float2*)&ws[(rb + 8) * WSTRIDE + s * 16 + kc];
            float2 ra3 = *(const float2*)&ws[(rb + 8) * WSTRIDE + s * 16 + 8 + kc];
            uint32_t A0h, A0l, A1h, A1l, A2h, A2l, A3h, A3l;
            bsplit(ra0, A0h, A0l);
            bsplit(ra1, A1h, A1l);
            bsplit(ra2, A2h, A2l);
            bsplit(ra3, A3h, A3l);

            #pragma unroll
            for (int g = 0; g < 4; g++) {
                const int base = ((s * 4 + g) << 6) + (lane << 1);
                uint2 bh = *(const uint2*)&sXh[base];
                uint2 bl = *(const uint2*)&sXl[base];
                mma_bf16(acc[g], A0h, A1h, A2h, A3h, bh.x, bh.y);
                mma_bf16(acc[g], A0h, A1h, A2h, A3h, bl.x, bl.y);
                mma_bf16(acc[g], A0l, A1l, A2l, A3l, bh.x, bh.y);
            }
        }
    }

    const int c = c0 + w * 16 + (lane >> 2);
    #pragma unroll
    for (int g = 0; g < 4; g++) {
        const int b = g * 8 + 2 * (lane & 3);
        out[(size_t)b * S + c]           = acc[g][0];
        out[(size_t)(b + 1) * S + c]     = acc[g][1];
        out[(size_t)b * S + c + 8]       = acc[g][2];
        out[(size_t)(b + 1) * S + c + 8] = acc[g][3];
    }
}

// ---------------- kernel 1: fused QKV GEMM ----------------
__global__ void __launch_bounds__(256) qkv_kernel(const float* __restrict__ x,
                                                  const float* __restrict__ Wq,
                                                  const float* __restrict__ Wk,
                                                  const float* __restrict__ Wv) {
    const int z = blockIdx.z;
    const float* W = (z == 0) ? Wq : (z == 1 ? Wk : Wv);
    float* out = ((z == 0) ? g_qp : (z == 1 ? g_kp : g_vp)) + (size_t)blockIdx.y * BS;
    gemm_bf16<(S / QKV_KSPLIT) / 32>(x, W, out, blockIdx.x * 128,
                                     blockIdx.y * (S / QKV_KSPLIT));
}

// ---------------- kernel 1b: combine qkv partials + per-256-chunk min/max ----------------
__global__ void combine_kernel() {
    __shared__ float r0[8], r1[8], r2[8], r3[8];
    const int tid = threadIdx.x;
    const int idx = blockIdx.x * 256 + tid;
    float q = 0.f, k = 0.f, v = 0.f;
    #pragma unroll
    for (int p = 0; p < QKV_KSPLIT; p++) {
        q += g_qp[(size_t)p * BS + idx];
        k += g_kp[(size_t)p * BS + idx];
        v += g_vp[(size_t)p * BS + idx];
    }
    g_qc[idx] = q; g_kc[idx] = k; g_vc[idx] = v;

    float qmn = q, qmx = q, kmn = k, kmx = k;
    #pragma unroll
    for (int off = 16; off > 0; off >>= 1) {
        qmn = fminf(qmn, __shfl_xor_sync(0xffffffffu, qmn, off));
        qmx = fmaxf(qmx, __shfl_xor_sync(0xffffffffu, qmx, off));
        kmn = fminf(kmn, __shfl_xor_sync(0xffffffffu, kmn, off));
        kmx = fmaxf(kmx, __shfl_xor_sync(0xffffffffu, kmx, off));
    }
    const int lane = tid & 31, wid = tid >> 5;
    if (lane == 0) { r0[wid] = qmn; r1[wid] = qmx; r2[wid] = kmn; r3[wid] = kmx; }
    __syncthreads();
    if (tid == 0) {
        float a = r0[0], b = r1[0], c = r2[0], d = r3[0];
        #pragma unroll
        for (int w = 1; w < 8; w++) {
            a = fminf(a, r0[w]); b = fmaxf(b, r1[w]);
            c = fminf(c, r2[w]); d = fmaxf(d, r3[w]);
        }
        g_rqmn[blockIdx.x] = a; g_rqmx[blockIdx.x] = b;
        g_rkmn[blockIdx.x] = c; g_rkmx[blockIdx.x] = d;
    }
}

// batch-level range + shift M (identical fp sequence wherever used)
__device__ __forceinline__ void batch_range(int b, float& c, float& h, float& M) {
    float qmn = 3.0e38f, qmx = -3.0e38f, kmn = 3.0e38f, kmx = -3.0e38f;
    #pragma unroll
    for (int j = 0; j < 8; j++) {
        qmn = fminf(qmn, g_rqmn[b * 8 + j]);
        qmx = fmaxf(qmx, g_rqmx[b * 8 + j]);
        kmn = fminf(kmn, g_rkmn[b * 8 + j]);
        kmx = fmaxf(kmx, g_rkmx[b * 8 + j]);
    }
    c = 0.5f * (qmn + qmx);
    h = fmaxf(0.5f * (qmx - qmn), 1e-30f);
    M = fmaxf(fmaxf(qmn * kmn, qmn * kmx), fmaxf(qmx * kmn, qmx * kmx));
}

// ---------------- kernel 2a: Chebyshev nodes (y<5) + q-moments (y==5) ----------------
// y<5:  F(t_n), G(t_n) for 8 nodes per block (1 per warp).
// y==5: S_m = sum_i T_m(u_i), m=0..NCHEB-1 (enables block-local Z downstream).
__global__ void __launch_bounds__(256) cheb_nodes_kernel() {
    __shared__ float sk[S], sv[S];
    __shared__ float sprm[3];
    __shared__ float sS[NCHEB][9];

    const int b = blockIdx.x;
    const int tid = threadIdx.x;
    const int lane = tid & 31, w = tid >> 5;

    if (tid == 0) {
        float c, h, M;
        batch_range(b, c, h, M);
        sprm[0] = c; sprm[1] = h; sprm[2] = M;
    }

    if (blockIdx.y == 5) {
        // ---- moments path ----
        __syncthreads();
        const float c = sprm[0], hinv = 1.0f / sprm[1];

        float acc[NCHEB];
        #pragma unroll
        for (int m = 0; m < NCHEB; m++) acc[m] = 0.f;

        #pragma unroll
        for (int jj = 0; jj < 8; jj++) {
            const int i = tid + jj * 256;
            float u = fminf(1.f, fmaxf(-1.f, (g_qc[b * S + i] - c) * hinv));
            float t0 = 1.f, t1 = u;
            acc[0] += t0;
            acc[1] += t1;
            #pragma unroll
            for (int m = 2; m < NCHEB; m++) {
                float tm = fmaf(u + u, t1, -t0);
                acc[m] += tm;
                t0 = t1; t1 = tm;
            }
        }
        #pragma unroll
        for (int m = 0; m < NCHEB; m++) {
            float s = acc[m];
            #pragma unroll
            for (int off = 16; off > 0; off >>= 1)
                s += __shfl_xor_sync(0xffffffffu, s, off);
            if (lane == 0) sS[m][w] = s;
        }
        __syncthreads();
        if (tid < NCHEB) {
            float s = 0.f;
            #pragma unroll
            for (int ww = 0; ww < 8; ww++) s += sS[tid][ww];
            g_S[b * NCHEB + tid] = s;
        }
        return;
    }

    // ---- nodes path ----
    for (int idx = tid; idx < S; idx += 256) {
        sk[idx] = g_kc[b * S + idx];
        sv[idx] = g_vc[b * S + idx];
    }
    __syncthreads();
    const float c = sprm[0], h = sprm[1], Ml2e = sprm[2] * L2E;

    const int n = blockIdx.y * 8 + w;
    const float t = fmaf(h, cospif((n + 0.5f) * (1.0f / NCHEB)), c);
    const float tl = t * L2E;
    float F = 0.f, G = 0.f;
    #pragma unroll 4
    for (int j = lane; j < S; j += 32) {
        float e = ex2f(fmaf(tl, sk[j], -Ml2e));
        F = fmaf(e, sv[j], F);
        G += e;
    }
    #pragma unroll
    for (int off = 16; off > 0; off >>= 1) {
        F += __shfl_xor_sync(0xffffffffu, F, off);
        G += __shfl_xor_sync(0xffffffffu, G, off);
    }
    if (lane == 0) {
        g_F[b * NCHEB + n] = F;
        g_G[b * NCHEB + n] = G;
    }
}

// ---------------- kernel 2b: coefficients + Z from moments + Clenshaw(F) + act ----------
// grid (BATCH, 8), block 256, 1 i per thread. Fully block-local (no cross-block Z).
__global__ void __launch_bounds__(256) cheb_evalact_kernel(const float* __restrict__ p2) {
    __shared__ float scos[NCHEB][NCHEB + 1];
    __shared__ float sF[NCHEB], sG[NCHEB], saF[NCHEB], saG[NCHEB], sS[NCHEB];
    __shared__ float sprm[2];
    __shared__ float sZ, sPs0, sPs1, sPs2;

    const int b = blockIdx.x;
    const int tid = threadIdx.x;

    if (tid == 0) {
        float c, h, M;
        batch_range(b, c, h, M);
        sprm[0] = c; sprm[1] = h;
    }
    if (tid == 32) {
        float p[5];
        #pragma unroll
        for (int t = 0; t < 5; t++) p[t] = p2[t];
        float pm = p[0];
        #pragma unroll
        for (int t = 1; t < 5; t++) pm = fmaxf(pm, p[t]);
        float pe[5], psum = 0.f;
        #pragma unroll
        for (int t = 0; t < 5; t++) { pe[t] = ex2f((p[t] - pm) * L2E); psum += pe[t]; }
        float inv = __fdividef(1.0f, psum);
        sPs0 = pe[0] * inv; sPs1 = pe[1] * inv; sPs2 = pe[2] * inv;
    }
    if (tid >= 64 && tid < 64 + NCHEB) {
        const int m = tid - 64;
        sF[m] = g_F[b * NCHEB + m];
        sG[m] = g_G[b * NCHEB + m];
        sS[m] = g_S[b * NCHEB + m];
    }
    for (int idx = tid; idx < NCHEB * NCHEB; idx += 256) {
        int m = idx / NCHEB, n = idx - m * NCHEB;
        scos[m][n] = cospif((float)(m * (2 * n + 1)) * (1.0f / (2 * NCHEB)));
    }
    __syncthreads();

    if (tid < 2 * NCHEB) {
        const int m = (tid < NCHEB) ? tid : (tid - NCHEB);
        const float* src = (tid < NCHEB) ? sF : sG;
        float s = 0.f;
        #pragma unroll 8
        for (int n = 0; n < NCHEB; n++)
            s = fmaf(src[n], scos[m][n], s);
        s *= (m == 0) ? (1.0f / NCHEB) : (2.0f / NCHEB);
        if (tid < NCHEB) saF[m] = s; else saG[m] = s;
    }
    __syncthreads();

    if (tid == 0) {
        // Z = sum_m a^G_m S_m  ( == sum_i G_interp(q_i) )
        float z = 0.f;
        #pragma unroll 8
        for (int m = 0; m < NCHEB; m++)
            z = fmaf(saG[m], sS[m], z);
        sZ = z;
    }
    __syncthreads();

    const float c = sprm[0], hinv = 1.0f / sprm[1];
    const float Z = sZ;
    const float ps0 = sPs0, ps1 = sPs1, ps2 = sPs2;

    const int i = blockIdx.y * 256 + tid;
    float t = g_qc[b * S + i];
    float u = fminf(1.f, fmaxf(-1.f, (t - c) * hinv));
    float u2 = u + u;
    float f1 = 0.f, f2 = 0.f;
    #pragma unroll
    for (int m = NCHEB - 1; m >= 1; m--) {
        float nf = fmaf(u2, f1, saF[m] - f2); f2 = f1; f1 = nf;
    }
    const float F = fmaf(u, f1, saF[0] - f2);

    const float val = __fdividef(F, Z);
    const float sig = __fdividef(1.0f, 1.0f + ex2f(-val * L2E));
    g_act[b * S + i] = sig * val * ps0 + __sinf(val) * ps1 + val * ps2;
}

// ---------------- kernel 4: fc2 GEMM, grid (16 ctiles, 16 ksplit) ----------------
__global__ void __launch_bounds__(256) fc2_kernel(const float* __restrict__ W) {
    gemm_bf16<(S / FC2_KSPLIT) / 32>(g_act, W, g_fcp + (size_t)blockIdx.y * BS,
                                     blockIdx.x * 128, blockIdx.y * (S / FC2_KSPLIT));
}

// ---------------- kernel 5: combine fc2 partials + bias + LayerNorm ----------------
__global__ void ln_kernel(const float* __restrict__ bias,
                          const float* __restrict__ g2,
                          const float* __restrict__ b2,
                          float* __restrict__ out) {
    __shared__ float sRow[S];
    __shared__ float rsum[16], rsq[16];
    __shared__ float sMu, sRstd;

    const int b = blockIdx.x;
    const int tid = threadIdx.x;
    const int lane = tid & 31, wid = tid >> 5;

    float s = 0.f, s2 = 0.f;
    #pragma unroll
    for (int it = 0; it < 4; it++) {
        int idx = tid + it * 512;
        float v = bias[idx];
        #pragma unroll
        for (int p = 0; p < FC2_KSPLIT; p++)
            v += g_fcp[(size_t)p * BS + b * S + idx];
        sRow[idx] = v;
        s += v;
        s2 = fmaf(v, v, s2);
    }
    #pragma unroll
    for (int off = 16; off > 0; off >>= 1) {
        s  += __shfl_xor_sync(0xffffffffu, s,  off);
        s2 += __shfl_xor_sync(0xffffffffu, s2, off);
    }
    if (lane == 0) { rsum[wid] = s; rsq[wid] = s2; }
    __syncthreads();
    if (tid == 0) {
        float ts = 0.f, ts2 = 0.f;
        #pragma unroll
        for (int w = 0; w < 16; w++) { ts += rsum[w]; ts2 += rsq[w]; }
        float mu = ts * (1.0f / S);
        float var = ts2 * (1.0f / S) - mu * mu;
        sMu = mu;
        sRstd = rsqrtf(var + EPSLN);
    }
    __syncthreads();

    const float mu = sMu, rstd = sRstd;
    #pragma unroll
    for (int it = 0; it < 4; it++) {
        int idx = tid + it * 512;
        out[b * S + idx] = (sRow[idx] - mu) * rstd * g2[idx] + b2[idx];
    }
}

// ---------------- launch ----------------
extern "C" void kernel_launch(void* const* d_in, const int* in_sizes, int n_in,
                              void* d_out, int out_size) {
    const float* x    = (const float*)d_in[0];
    const float* Wq   = (const float*)d_in[1];
    const float* Wk   = (const float*)d_in[2];
    const float* Wv   = (const float*)d_in[3];
    const float* p2   = (const float*)d_in[4];
    const float* Wfc2 = (const float*)d_in[5];
    const float* bfc2 = (const float*)d_in[6];
    const float* g2   = (const float*)d_in[7];
    const float* b2   = (const float*)d_in[8];
    float* out = (float*)d_out;

    qkv_kernel<<<dim3(16, QKV_KSPLIT, 3), 256>>>(x, Wq, Wk, Wv);
    combine_kernel<<<BS / 256, 256>>>();
    cheb_nodes_kernel<<<dim3(BATCH, 6), 256>>>();
    cheb_evalact_kernel<<<dim3(BATCH, 8), 256>>>(p2);
    fc2_kernel<<<dim3(16, FC2_KSPLIT), 256>>>(Wfc2);
    ln_kernel<<<BATCH, 512>>>(bfc2, g2, b2, out);
}